// round 11
// baseline (speedup 1.0000x reference)
#include <cuda_runtime.h>
#include <cuda_bf16.h>
#include <cstdint>
#include <cstring>

// ---------------- constants ----------------
constexpr int NP = 8192;
constexpr int WTOT = 23592960;
constexpr int PER_BLK_W = 737280;
constexpr size_t WP_PER_BLK = 2949120;     // 4 bytes per weight (hi+lo bf16)
constexpr size_t MP_PER_BLK = 147456;

// ---------------- device scratch ----------------
__device__ char g_wpc[32 * WP_PER_BLK];
__device__ char g_mpc[32 * MP_PER_BLK];
__device__ float g_Xa[NP * 192], g_Xb[NP * 192];
__device__ __nv_bfloat16 g_XaH[NP * 192], g_XaL[NP * 192];
__device__ __nv_bfloat16 g_XbH[NP * 192], g_XbL[NP * 192];
__device__ __nv_bfloat16 g_T1H[NP * 128], g_T1L[NP * 128];
__device__ __nv_bfloat16 g_T2H[NP * 128], g_T2L[NP * 128];

// ---------------- helpers ----------------
__device__ __forceinline__ uint32_t smem_u32(const void* p) {
    uint32_t a;
    asm("{ .reg .u64 t; cvta.to.shared.u64 t, %1; cvt.u32.u64 %0, t; }" : "=r"(a) : "l"(p));
    return a;
}
__device__ __forceinline__ unsigned short f2bf(float v) {
    __nv_bfloat16 b = __float2bfloat16(v);
    unsigned short u; memcpy(&u, &b, 2);
    return u;
}
__device__ __forceinline__ float bf2f(unsigned short u) {
    __nv_bfloat16 b; memcpy(&b, &u, 2);
    return __bfloat162float(b);
}
__device__ __forceinline__ void ldm4(uint32_t* r, uint32_t addr) {
    asm volatile("ldmatrix.sync.aligned.m8n8.x4.shared.b16 {%0,%1,%2,%3}, [%4];"
        : "=r"(r[0]), "=r"(r[1]), "=r"(r[2]), "=r"(r[3]) : "r"(addr));
}
__device__ __forceinline__ void ldm2(uint32_t* r, uint32_t addr) {
    asm volatile("ldmatrix.sync.aligned.m8n8.x2.shared.b16 {%0,%1}, [%2];"
        : "=r"(r[0]), "=r"(r[1]) : "r"(addr));
}
__device__ __forceinline__ void mma16816(float* d, const uint32_t* a, uint32_t b0, uint32_t b1) {
    asm volatile("mma.sync.aligned.m16n8k16.row.col.f32.bf16.bf16.f32 "
        "{%0,%1,%2,%3},{%4,%5,%6,%7},{%8,%9},{%0,%1,%2,%3};"
        : "+f"(d[0]), "+f"(d[1]), "+f"(d[2]), "+f"(d[3])
        : "r"(a[0]), "r"(a[1]), "r"(a[2]), "r"(a[3]), "r"(b0), "r"(b1));
}
__device__ __forceinline__ void cpa16(uint32_t dst, const void* src, uint32_t srcsz) {
    asm volatile("cp.async.cg.shared.global [%0], [%1], 16, %2;"
        :: "r"(dst), "l"(src), "r"(srcsz) : "memory");
}
#define CP_COMMIT() asm volatile("cp.async.commit_group;" ::: "memory")
#define CP_WAIT0()  asm volatile("cp.async.wait_group 0;" ::: "memory")

// ---------------- weight prepack (convs) ----------------
// Per conv j, per tap: [hi OC x IC bf16][lo OC x IC bf16], dense rows.
__global__ void k_wp(const float* __restrict__ wf) {
    int idx = blockIdx.x * 256 + threadIdx.x;
    if (idx >= WTOT) return;
    int blk = idx / PER_BLK_W;
    int r = idx - blk * PER_BLK_W;
    const int starts[6] = {0, 110592, 258048, 368640, 479232, 626688};
    const size_t pre[6] = {0, 442368, 1032192, 1474560, 1916928, 2506752};
    int j = 0;
#pragma unroll
    for (int t = 1; t < 6; t++) if (r >= starts[t]) j = t;
    int off = r - starts[j];
    int oc = ((j % 3) == 2) ? 96 : 128;
    int ic = ((j % 3) == 0) ? 96 : 128;
    int o = off / (ic * 9);
    int rem = off - o * ic * 9;
    int c = rem / 9;
    int tap = rem - c * 9;
    float v = wf[idx];
    unsigned short hb = f2bf(v);
    unsigned short lb = f2bf(v - bf2f(hb));
    size_t base = (size_t)blk * WP_PER_BLK + pre[j] + (size_t)tap * (oc * ic * 4);
    size_t e = (size_t)(o * ic + c) * 2;
    *(unsigned short*)(g_wpc + base + e) = hb;
    *(unsigned short*)(g_wpc + base + (size_t)oc * ic * 2 + e) = lb;
}

// ---------------- mixing prepack: [hi 192x192][lo 192x192] ----------------
__global__ void k_mp(const float* __restrict__ m) {
    int idx = blockIdx.x * 256 + threadIdx.x;
    if (idx >= 32 * 36864) return;
    int blk = idx / 36864;
    int r = idx - blk * 36864;
    float v = m[idx];
    unsigned short hb = f2bf(v);
    unsigned short lb = f2bf(v - bf2f(hb));
    size_t base = (size_t)blk * MP_PER_BLK;
    *(unsigned short*)(g_mpc + base + (size_t)r * 2) = hb;
    *(unsigned short*)(g_mpc + base + 73728 + (size_t)r * 2) = lb;
}

// ---------------- normalize + permute + space_to_depth -> NHWC ----------------
__global__ void k_pre(const float* __restrict__ x, const float* __restrict__ mu,
                      const float* __restrict__ sigma, const int* __restrict__ perm,
                      float* __restrict__ Xo, __nv_bfloat16* __restrict__ XoH,
                      __nv_bfloat16* __restrict__ XoL) {
    int idx = blockIdx.x * 256 + threadIdx.x;
    if (idx >= NP * 192) return;
    int ch = idx % 192;
    int p = idx / 192;
    int w = p & 31, h = (p >> 5) & 31, b = p >> 10;
    int c = ch >> 6, r = ch & 63;
    int bi = r >> 3, bj = r & 7;
    int flat = (h * 8 + bi) * 256 + (w * 8 + bj);
    int src = perm[c * 65536 + flat];
    float v = (x[(b * 3 + c) * 65536 + src] - mu[c]) / sigma[c];
    Xo[idx] = v;
    unsigned short hb = f2bf(v);
    XoH[idx] = *(__nv_bfloat16*)&hb;
    unsigned short lb = f2bf(v - bf2f(hb));
    XoL[idx] = *(__nv_bfloat16*)&lb;
}

// ---------------- final NHWC -> NCHW ----------------
__global__ void k_post(const float* __restrict__ X, float* __restrict__ out) {
    int idx = blockIdx.x * 256 + threadIdx.x;
    if (idx >= NP * 192) return;
    int w = idx & 31;
    int h = (idx >> 5) & 31;
    int ch = (idx >> 10) % 192;
    int b = idx / (192 * 1024);
    out[idx] = X[(((b * 32 + h) * 32 + w) * 192) + ch];
}

// ---------------- warp-mma bf16x3 implicit-GEMM conv, halo-A + K-split warps ----------------
// CTA = 64 positions x full OC, 512 threads, 16 warps as 2M x 4N x 2K:
// warp tile = 32 rows x OC/4 cols x IC/2 k. Halo-A loaded once; per-stage
// B-only copy (NBUF buffers). K-halves reduced via smem at the end.
template <int IC, int OC, int KS, bool RELU, bool ADDIN>
__global__ __launch_bounds__(512, 1) void k_mma(
    const __nv_bfloat16* __restrict__ inH, const __nv_bfloat16* __restrict__ inL,
    int in_stride,
    const char* __restrict__ wp,
    const float* __restrict__ bias,
    const float* __restrict__ addp, int add_stride,
    float* __restrict__ out,
    __nv_bfloat16* __restrict__ outH, __nv_bfloat16* __restrict__ outL,
    int out_stride)
{
    constexpr int PH = KS / 2;
    constexpr int HR = 2 + 2 * PH;       // halo rows
    constexpr int HC = 32 + 2 * PH;      // halo cols
    constexpr int NPOS = HR * HC;
    constexpr int NST = KS * KS;
    constexpr int NBUF = (NST > 1) ? 2 : 1;
    constexpr int KST = IC / 16;
    constexpr int KHALF = KST / 2;       // ksteps per warp (K-split)
    constexpr int CPR = IC / 8;
    constexpr int LDC = IC + 8;          // padded channel stride (b16 units)
    constexpr int LDCb = LDC * 2;
    constexpr int NT = OC / 32;          // n8 tiles per warp (warp N = OC/4)
    constexpr int NP2 = NT / 2;
    constexpr int TAIL = NT & 1;
    constexpr int ASZ = NPOS * LDC;      // b16 per A plane
    constexpr int BSZ = OC * LDC;        // b16 per B plane buffer

    extern __shared__ __align__(16) unsigned short smem[];
    unsigned short* Ah = smem;
    unsigned short* Al = Ah + ASZ;
    unsigned short* Bh = Al + ASZ;
    unsigned short* Bl = Bh + NBUF * BSZ;

    const int tid = threadIdx.x;
    const int wid = tid >> 5, lane = tid & 31;
    const int wm = wid & 1;
    const int wn = (wid >> 1) & 3;
    const int kh = wid >> 3;             // K-half 0/1
    const int p0 = blockIdx.x * 64;
    const int b = p0 >> 10;
    const int h0 = (p0 >> 5) & 31;

    float acc[2][NT][4];
#pragma unroll
    for (int i = 0; i < 2; i++)
#pragma unroll
        for (int j = 0; j < NT; j++)
#pragma unroll
            for (int q = 0; q < 4; q++) acc[i][j][q] = 0.f;

    const uint32_t sAh = smem_u32(Ah), sAl = smem_u32(Al);
    const uint32_t sBh = smem_u32(Bh), sBl = smem_u32(Bl);
    const uint32_t kofs = (uint32_t)(kh * KHALF) * 32;   // byte offset of this warp's k range

    // A fragment per-lane halo pixel offsets (bytes), one per mt
    uint32_t apix[2];
#pragma unroll
    for (int mt = 0; mt < 2; mt++) {
        int p = wm * 32 + mt * 16 + (lane & 15);
        apix[mt] = (uint32_t)(((p >> 5) * HC + (p & 31)) * LDCb) + ((lane >> 4) * 16) + kofs;
    }

    // ---- prologue: A halo copy (once) ----
#pragma unroll 4
    for (int i = tid; i < NPOS * CPR; i += 512) {
        int pos = i / CPR, ck = i - pos * CPR;
        int hr = pos / HC, hc = pos - hr * HC;
        int hh = h0 + hr - PH, ww = hc - PH;
        bool ok = (hh >= 0) && (hh < 32) && (ww >= 0) && (ww < 32);
        size_t off = ok ? ((size_t)(((b << 5) + hh) * 32 + ww) * in_stride + ck * 8) : 0;
        uint32_t sz = ok ? 16u : 0u;
        uint32_t d = (uint32_t)(pos * LDC + ck * 8) * 2;
        cpa16(sAh + d, inH + off, sz);
        cpa16(sAl + d, inL + off, sz);
    }

    auto issueB = [&](int s, int buf) {
        const char* bu = wp + (size_t)s * (OC * IC * 4);
#pragma unroll
        for (int i = tid; i < OC * CPR; i += 512) {
            int rr = i / CPR, ck = i - rr * CPR;
            size_t so = (size_t)(rr * IC + ck * 8) * 2;
            uint32_t d = (uint32_t)(buf * BSZ + rr * LDC + ck * 8) * 2;
            cpa16(sBh + d, bu + so, 16);
            cpa16(sBl + d, bu + (size_t)OC * IC * 2 + so, 16);
        }
        CP_COMMIT();
    };

    issueB(0, 0);   // commits A + B0 together

    for (int s = 0; s < NST; s++) {
        CP_WAIT0();
        __syncthreads();
        if (s + 1 < NST) issueB(s + 1, (s + 1) & 1);

        const uint32_t hoffb = (uint32_t)(((s / KS) * HC + (s - (s / KS) * KS)) * LDCb);
        const uint32_t aAh = sAh + hoffb;
        const uint32_t aAl = sAl + hoffb;
        const uint32_t aBh = sBh + (uint32_t)((s & (NBUF - 1)) * BSZ) * 2;
        const uint32_t aBl = sBl + (uint32_t)((s & (NBUF - 1)) * BSZ) * 2;

        uint32_t fah[2][2][4], fal[2][2][4];
        uint32_t fbh[2][NP2 ? NP2 : 1][4], fbl[2][NP2 ? NP2 : 1][4];
        uint32_t fth[2][2], ftl[2][2];

        auto ldfrag = [&](int ks, int fb) {
#pragma unroll
            for (int mt = 0; mt < 2; mt++) {
                uint32_t ro = apix[mt] + (uint32_t)ks * 32;
                ldm4(fah[fb][mt], aAh + ro);
                ldm4(fal[fb][mt], aAl + ro);
            }
#pragma unroll
            for (int p = 0; p < NP2; p++) {
                uint32_t ro = (uint32_t)(wn * (OC / 4) + p * 16 + (lane & 15)) * LDCb
                            + kofs + (uint32_t)ks * 32 + ((lane >> 4) * 16);
                ldm4(fbh[fb][p], aBh + ro);
                ldm4(fbl[fb][p], aBl + ro);
            }
            if (TAIL) {
                uint32_t ro = (uint32_t)(wn * (OC / 4) + NP2 * 16 + (lane & 7)) * LDCb
                            + kofs + (uint32_t)ks * 32 + (((lane >> 3) & 1) * 16);
                ldm2(fth[fb], aBh + ro);
                ldm2(ftl[fb], aBl + ro);
            }
        };

        ldfrag(0, 0);
#pragma unroll
        for (int ks = 0; ks < KHALF; ks++) {
            if (ks + 1 < KHALF) ldfrag(ks + 1, (ks + 1) & 1);
            const int fb = ks & 1;
#pragma unroll
            for (int p = 0; p < NP2; p++) {
#pragma unroll
                for (int sub = 0; sub < 2; sub++) {
#pragma unroll
                    for (int mt = 0; mt < 2; mt++) {
                        float* d = acc[mt][p * 2 + sub];
                        mma16816(d, fah[fb][mt], fbh[fb][p][sub], fbh[fb][p][sub + 2]);
                        mma16816(d, fah[fb][mt], fbl[fb][p][sub], fbl[fb][p][sub + 2]);
                        mma16816(d, fal[fb][mt], fbh[fb][p][sub], fbh[fb][p][sub + 2]);
                    }
                }
            }
            if (TAIL) {
#pragma unroll
                for (int mt = 0; mt < 2; mt++) {
                    float* d = acc[mt][NT - 1];
                    mma16816(d, fah[fb][mt], fth[fb][0], fth[fb][1]);
                    mma16816(d, fah[fb][mt], ftl[fb][0], ftl[fb][1]);
                    mma16816(d, fal[fb][mt], fth[fb][0], fth[fb][1]);
                }
            }
        }
    }

    // ---- K-half reduction via smem (overlays dead A region) ----
    float* Red = (float*)smem;            // 64 x OC fp32 = <= 49KB, fits in A region
    const int l4 = lane >> 2, l2 = (lane & 3) * 2;
    __syncthreads();
    if (kh == 1) {
#pragma unroll
        for (int nt = 0; nt < NT; nt++) {
            const int col = wn * (OC / 4) + nt * 8 + l2;
#pragma unroll
            for (int mt = 0; mt < 2; mt++) {
                const int row = wm * 32 + mt * 16 + l4;
                float* d = acc[mt][nt];
                *(float2*)(Red + row * OC + col) = make_float2(d[0], d[1]);
                *(float2*)(Red + (row + 8) * OC + col) = make_float2(d[2], d[3]);
            }
        }
    }
    __syncthreads();

    // ---- epilogue (kh == 0 warps only) ----
    if (kh == 0) {
#pragma unroll
        for (int nt = 0; nt < NT; nt++) {
            const int col = wn * (OC / 4) + nt * 8 + l2;
            float b0 = 0.f, b1 = 0.f;
            if (bias) { b0 = bias[col]; b1 = bias[col + 1]; }
#pragma unroll
            for (int mt = 0; mt < 2; mt++) {
                const int row = wm * 32 + mt * 16 + l4;
                const int pr = p0 + row;
                float* d = acc[mt][nt];
                float2 r0 = *(float2*)(Red + row * OC + col);
                float2 r1 = *(float2*)(Red + (row + 8) * OC + col);
                float v0 = d[0] + r0.x + b0, v1 = d[1] + r0.y + b1;
                float v2 = d[2] + r1.x + b0, v3 = d[3] + r1.y + b1;
                if (RELU) {
                    v0 = fmaxf(v0, 0.f); v1 = fmaxf(v1, 0.f);
                    v2 = fmaxf(v2, 0.f); v3 = fmaxf(v3, 0.f);
                }
                if (ADDIN) {
                    float2 a0 = *(const float2*)(addp + (size_t)pr * add_stride + col);
                    float2 a1 = *(const float2*)(addp + (size_t)(pr + 8) * add_stride + col);
                    v0 += a0.x; v1 += a0.y; v2 += a1.x; v3 += a1.y;
                }
                if (out) {
                    *(float2*)(out + (size_t)pr * out_stride + col) = make_float2(v0, v1);
                    *(float2*)(out + (size_t)(pr + 8) * out_stride + col) = make_float2(v2, v3);
                }
                __nv_bfloat162 h01 = __float22bfloat162_rn(make_float2(v0, v1));
                __nv_bfloat162 h23 = __float22bfloat162_rn(make_float2(v2, v3));
                float2 f01 = __bfloat1622float2(h01);
                float2 f23 = __bfloat1622float2(h23);
                __nv_bfloat162 l01 = __float22bfloat162_rn(make_float2(v0 - f01.x, v1 - f01.y));
                __nv_bfloat162 l23 = __float22bfloat162_rn(make_float2(v2 - f23.x, v3 - f23.y));
                *(__nv_bfloat162*)(outH + (size_t)pr * out_stride + col) = h01;
                *(__nv_bfloat162*)(outH + (size_t)(pr + 8) * out_stride + col) = h23;
                *(__nv_bfloat162*)(outL + (size_t)pr * out_stride + col) = l01;
                *(__nv_bfloat162*)(outL + (size_t)(pr + 8) * out_stride + col) = l23;
            }
        }
    }
}

// ---------------- launch ----------------
extern "C" void kernel_launch(void* const* d_in, const int* in_sizes, int n_in,
                              void* d_out, int out_size) {
    const float* x     = (const float*)d_in[0];
    const float* mu    = (const float*)d_in[1];
    const float* sigma = (const float*)d_in[2];
    const float* wf    = (const float*)d_in[3];
    const float* bfl   = (const float*)d_in[4];
    const float* m     = (const float*)d_in[5];
    const int*   perm  = (const int*)d_in[6];
    float* out = (float*)d_out;

    char *wp, *mp;
    float *Xa, *Xb;
    __nv_bfloat16 *XaH, *XaL, *XbH, *XbL, *T1H, *T1L, *T2H, *T2L;
    cudaGetSymbolAddress((void**)&wp, g_wpc);
    cudaGetSymbolAddress((void**)&mp, g_mpc);
    cudaGetSymbolAddress((void**)&Xa, g_Xa);
    cudaGetSymbolAddress((void**)&Xb, g_Xb);
    cudaGetSymbolAddress((void**)&XaH, g_XaH);
    cudaGetSymbolAddress((void**)&XaL, g_XaL);
    cudaGetSymbolAddress((void**)&XbH, g_XbH);
    cudaGetSymbolAddress((void**)&XbL, g_XbL);
    cudaGetSymbolAddress((void**)&T1H, g_T1H);
    cudaGetSymbolAddress((void**)&T1L, g_T1L);
    cudaGetSymbolAddress((void**)&T2H, g_T2H);
    cudaGetSymbolAddress((void**)&T2L, g_T2L);

    // dynamic smem bytes: 4*(NPOS*LDC) + NBUF*4*(OC*LDC)
    const int SM_C1 = 4 * (136 * 104) + 2 * 4 * (128 * 104);   // 163,072
    const int SM_C2 = 4 * (136 * 136) + 2 * 4 * (128 * 136);   // 213,248
    const int SM_C3 = 4 * (136 * 136) + 2 * 4 * (96 * 136);    // 178,432
    const int SM_MX = 4 * (64 * 200) + 1 * 4 * (192 * 200);    // 204,800
    static bool attr_done = false;
    if (!attr_done) {
        cudaFuncSetAttribute(k_mma<96, 128, 3, true, false>,  cudaFuncAttributeMaxDynamicSharedMemorySize, SM_C1);
        cudaFuncSetAttribute(k_mma<128, 128, 3, true, false>, cudaFuncAttributeMaxDynamicSharedMemorySize, SM_C2);
        cudaFuncSetAttribute(k_mma<128, 96, 3, false, true>,  cudaFuncAttributeMaxDynamicSharedMemorySize, SM_C3);
        cudaFuncSetAttribute(k_mma<192, 192, 1, false, false>, cudaFuncAttributeMaxDynamicSharedMemorySize, SM_MX);
        attr_done = true;
    }

    k_wp<<<(WTOT + 255) / 256, 256>>>(wf);
    k_mp<<<(32 * 36864 + 255) / 256, 256>>>(m);
    k_pre<<<(NP * 192 + 255) / 256, 256>>>(x, mu, sigma, perm, Xa, XaH, XaL);

    const size_t pre_j[6] = {0, 442368, 1032192, 1474560, 1916928, 2506752};
    const int bstart[6] = {0, 128, 256, 352, 480, 608};

    float* X = Xa;  __nv_bfloat16 *XH = XaH, *XL = XaL;
    float* Y = Xb;  __nv_bfloat16 *YH = XbH, *YL = XbL;
    for (int blk = 0; blk < 32; blk++) {
        const char* wb = wp + (size_t)blk * WP_PER_BLK;
        const float* bb = bfl + blk * 704;
        // round 0: x1 += f0(x2)
        k_mma<96, 128, 3, true, false><<<128, 512, SM_C1>>>(XH + 96, XL + 96, 192, wb + pre_j[0], bb + bstart[0], nullptr, 0, nullptr, T1H, T1L, 128);
        k_mma<128, 128, 3, true, false><<<128, 512, SM_C2>>>(T1H, T1L, 128, wb + pre_j[1], bb + bstart[1], nullptr, 0, nullptr, T2H, T2L, 128);
        k_mma<128, 96, 3, false, true><<<128, 512, SM_C3>>>(T2H, T2L, 128, wb + pre_j[2], bb + bstart[2], X + 0, 192, X + 0, XH + 0, XL + 0, 192);
        // round 1: x2 += f1(x1)
        k_mma<96, 128, 3, true, false><<<128, 512, SM_C1>>>(XH + 0, XL + 0, 192, wb + pre_j[3], bb + bstart[3], nullptr, 0, nullptr, T1H, T1L, 128);
        k_mma<128, 128, 3, true, false><<<128, 512, SM_C2>>>(T1H, T1L, 128, wb + pre_j[4], bb + bstart[4], nullptr, 0, nullptr, T2H, T2L, 128);
        k_mma<128, 96, 3, false, true><<<128, 512, SM_C3>>>(T2H, T2L, 128, wb + pre_j[5], bb + bstart[5], X + 96, 192, X + 96, XH + 96, XL + 96, 192);
        // 1x1 mixing
        k_mma<192, 192, 1, false, false><<<128, 512, SM_MX>>>(XH, XL, 192, mp + (size_t)blk * MP_PER_BLK, nullptr, nullptr, 0, Y, YH, YL, 192);
        float* tf = X; X = Y; Y = tf;
        __nv_bfloat16* th = XH; XH = YH; YH = th;
        __nv_bfloat16* tl = XL; XL = YL; YL = tl;
    }

    k_post<<<(NP * 192 + 255) / 256, 256>>>(X, out);
}

// round 12
// speedup vs baseline: 1.0137x; 1.0137x over previous
#include <cuda_runtime.h>
#include <cuda_bf16.h>
#include <cstdint>
#include <cstring>

// ---------------- constants ----------------
constexpr int NP = 8192;
constexpr int WTOT = 23592960;
constexpr int PER_BLK_W = 737280;
constexpr size_t WP_PER_BLK = 2949120;     // 4 bytes per weight (hi+lo bf16)
constexpr size_t MP_PER_BLK = 147456;

// ---------------- device scratch ----------------
__device__ char g_wpc[32 * WP_PER_BLK];
__device__ char g_mpc[32 * MP_PER_BLK];
__device__ float g_Xa[NP * 192], g_Xb[NP * 192];
__device__ __nv_bfloat16 g_XaH[NP * 192], g_XaL[NP * 192];
__device__ __nv_bfloat16 g_XbH[NP * 192], g_XbL[NP * 192];
__device__ __nv_bfloat16 g_T1H[NP * 128], g_T1L[NP * 128];
__device__ __nv_bfloat16 g_T2H[NP * 128], g_T2L[NP * 128];

// ---------------- helpers ----------------
__device__ __forceinline__ uint32_t smem_u32(const void* p) {
    uint32_t a;
    asm("{ .reg .u64 t; cvta.to.shared.u64 t, %1; cvt.u32.u64 %0, t; }" : "=r"(a) : "l"(p));
    return a;
}
__device__ __forceinline__ unsigned short f2bf(float v) {
    __nv_bfloat16 b = __float2bfloat16(v);
    unsigned short u; memcpy(&u, &b, 2);
    return u;
}
__device__ __forceinline__ float bf2f(unsigned short u) {
    __nv_bfloat16 b; memcpy(&b, &u, 2);
    return __bfloat162float(b);
}
__device__ __forceinline__ void ldm4(uint32_t* r, uint32_t addr) {
    asm volatile("ldmatrix.sync.aligned.m8n8.x4.shared.b16 {%0,%1,%2,%3}, [%4];"
        : "=r"(r[0]), "=r"(r[1]), "=r"(r[2]), "=r"(r[3]) : "r"(addr));
}
__device__ __forceinline__ void ldm2(uint32_t* r, uint32_t addr) {
    asm volatile("ldmatrix.sync.aligned.m8n8.x2.shared.b16 {%0,%1}, [%2];"
        : "=r"(r[0]), "=r"(r[1]) : "r"(addr));
}
__device__ __forceinline__ void mma16816(float* d, const uint32_t* a, uint32_t b0, uint32_t b1) {
    asm volatile("mma.sync.aligned.m16n8k16.row.col.f32.bf16.bf16.f32 "
        "{%0,%1,%2,%3},{%4,%5,%6,%7},{%8,%9},{%0,%1,%2,%3};"
        : "+f"(d[0]), "+f"(d[1]), "+f"(d[2]), "+f"(d[3])
        : "r"(a[0]), "r"(a[1]), "r"(a[2]), "r"(a[3]), "r"(b0), "r"(b1));
}
__device__ __forceinline__ void cpa16(uint32_t dst, const void* src, uint32_t srcsz) {
    asm volatile("cp.async.cg.shared.global [%0], [%1], 16, %2;"
        :: "r"(dst), "l"(src), "r"(srcsz) : "memory");
}
#define CP_COMMIT() asm volatile("cp.async.commit_group;" ::: "memory")
#define CP_WAIT0()  asm volatile("cp.async.wait_group 0;" ::: "memory")

// ---------------- weight prepack (convs) ----------------
// Per conv j, per tap: [hi OC x IC bf16][lo OC x IC bf16], dense rows.
__global__ void k_wp(const float* __restrict__ wf) {
    int idx = blockIdx.x * 256 + threadIdx.x;
    if (idx >= WTOT) return;
    int blk = idx / PER_BLK_W;
    int r = idx - blk * PER_BLK_W;
    const int starts[6] = {0, 110592, 258048, 368640, 479232, 626688};
    const size_t pre[6] = {0, 442368, 1032192, 1474560, 1916928, 2506752};
    int j = 0;
#pragma unroll
    for (int t = 1; t < 6; t++) if (r >= starts[t]) j = t;
    int off = r - starts[j];
    int oc = ((j % 3) == 2) ? 96 : 128;
    int ic = ((j % 3) == 0) ? 96 : 128;
    int o = off / (ic * 9);
    int rem = off - o * ic * 9;
    int c = rem / 9;
    int tap = rem - c * 9;
    float v = wf[idx];
    unsigned short hb = f2bf(v);
    unsigned short lb = f2bf(v - bf2f(hb));
    size_t base = (size_t)blk * WP_PER_BLK + pre[j] + (size_t)tap * (oc * ic * 4);
    size_t e = (size_t)(o * ic + c) * 2;
    *(unsigned short*)(g_wpc + base + e) = hb;
    *(unsigned short*)(g_wpc + base + (size_t)oc * ic * 2 + e) = lb;
}

// ---------------- mixing prepack: [hi 192x192][lo 192x192] ----------------
__global__ void k_mp(const float* __restrict__ m) {
    int idx = blockIdx.x * 256 + threadIdx.x;
    if (idx >= 32 * 36864) return;
    int blk = idx / 36864;
    int r = idx - blk * 36864;
    float v = m[idx];
    unsigned short hb = f2bf(v);
    unsigned short lb = f2bf(v - bf2f(hb));
    size_t base = (size_t)blk * MP_PER_BLK;
    *(unsigned short*)(g_mpc + base + (size_t)r * 2) = hb;
    *(unsigned short*)(g_mpc + base + 73728 + (size_t)r * 2) = lb;
}

// ---------------- normalize + permute + space_to_depth -> NHWC ----------------
__global__ void k_pre(const float* __restrict__ x, const float* __restrict__ mu,
                      const float* __restrict__ sigma, const int* __restrict__ perm,
                      float* __restrict__ Xo, __nv_bfloat16* __restrict__ XoH,
                      __nv_bfloat16* __restrict__ XoL) {
    int idx = blockIdx.x * 256 + threadIdx.x;
    if (idx >= NP * 192) return;
    int ch = idx % 192;
    int p = idx / 192;
    int w = p & 31, h = (p >> 5) & 31, b = p >> 10;
    int c = ch >> 6, r = ch & 63;
    int bi = r >> 3, bj = r & 7;
    int flat = (h * 8 + bi) * 256 + (w * 8 + bj);
    int src = perm[c * 65536 + flat];
    float v = (x[(b * 3 + c) * 65536 + src] - mu[c]) / sigma[c];
    Xo[idx] = v;
    unsigned short hb = f2bf(v);
    XoH[idx] = *(__nv_bfloat16*)&hb;
    unsigned short lb = f2bf(v - bf2f(hb));
    XoL[idx] = *(__nv_bfloat16*)&lb;
}

// ---------------- final NHWC -> NCHW ----------------
__global__ void k_post(const float* __restrict__ X, float* __restrict__ out) {
    int idx = blockIdx.x * 256 + threadIdx.x;
    if (idx >= NP * 192) return;
    int w = idx & 31;
    int h = (idx >> 5) & 31;
    int ch = (idx >> 10) % 192;
    int b = idx / (192 * 1024);
    out[idx] = X[(((b * 32 + h) * 32 + w) * 192) + ch];
}

// ---------------- warp-mma bf16x3 implicit-GEMM conv ----------------
// CTA = 64 positions x full OC, 8 warps (2M x 4N, warp 32x32). Halo-A loaded
// once; per-stage B copy where stage = (tap, K-chunk of CHK cols), double
// buffered. Inner kstep: single-buffered frags, TERM-MAJOR mma order (all
// tiles' hh, then hl, then lh) to break accumulator RAW chains.
template <int IC, int OC, int KS, int CHK, bool RELU, bool ADDIN>
__global__ __launch_bounds__(256, 1) void k_mma(
    const __nv_bfloat16* __restrict__ inH, const __nv_bfloat16* __restrict__ inL,
    int in_stride,
    const char* __restrict__ wp,
    const float* __restrict__ bias,
    const float* __restrict__ addp, int add_stride,
    float* __restrict__ out,
    __nv_bfloat16* __restrict__ outH, __nv_bfloat16* __restrict__ outL,
    int out_stride)
{
    constexpr int PH = KS / 2;
    constexpr int HR = 2 + 2 * PH;       // halo rows
    constexpr int HC = 32 + 2 * PH;      // halo cols
    constexpr int NPOS = HR * HC;
    constexpr int NCHK = IC / CHK;       // K-chunks per tap
    constexpr int NSTB = KS * KS * NCHK; // B stages
    constexpr int NBUF = (NSTB > 1) ? 2 : 1;
    constexpr int KSTC = CHK / 16;       // ksteps per stage
    constexpr int CPRA = IC / 8;         // 16B chunks per A row
    constexpr int CPRB = CHK / 8;        // 16B chunks per B row per stage
    constexpr int LDCA = IC + 8;         // A channel stride (b16)
    constexpr int LDCAb = LDCA * 2;
    constexpr int LDCB = CHK + 8;        // B col stride (b16)
    constexpr int LDCBb = LDCB * 2;
    constexpr int NT = OC / 32;          // n8 tiles per warp
    constexpr int NP2 = NT / 2;
    constexpr int TAIL = NT & 1;
    constexpr int ASZ = NPOS * LDCA;     // b16 per A plane
    constexpr int BSZ = OC * LDCB;       // b16 per B plane buffer

    extern __shared__ __align__(16) unsigned short smem[];
    unsigned short* Ah = smem;
    unsigned short* Al = Ah + ASZ;
    unsigned short* Bh = Al + ASZ;
    unsigned short* Bl = Bh + NBUF * BSZ;

    const int tid = threadIdx.x;
    const int wid = tid >> 5, lane = tid & 31;
    const int wm = wid & 1, wn = wid >> 1;
    const int p0 = blockIdx.x * 64;
    const int b = p0 >> 10;
    const int h0 = (p0 >> 5) & 31;

    float acc[2][NT][4];
#pragma unroll
    for (int i = 0; i < 2; i++)
#pragma unroll
        for (int j = 0; j < NT; j++)
#pragma unroll
            for (int q = 0; q < 4; q++) acc[i][j][q] = 0.f;

    const uint32_t sAh = smem_u32(Ah), sAl = smem_u32(Al);
    const uint32_t sBh = smem_u32(Bh), sBl = smem_u32(Bl);

    // A fragment per-lane halo pixel offsets (bytes), one per mt
    uint32_t apix[2];
#pragma unroll
    for (int mt = 0; mt < 2; mt++) {
        int p = wm * 32 + mt * 16 + (lane & 15);
        apix[mt] = (uint32_t)(((p >> 5) * HC + (p & 31)) * LDCAb) + ((lane >> 4) * 16);
    }

    // ---- prologue: A halo copy (once) ----
#pragma unroll 4
    for (int i = tid; i < NPOS * CPRA; i += 256) {
        int pos = i / CPRA, ck = i - pos * CPRA;
        int hr = pos / HC, hc = pos - hr * HC;
        int hh = h0 + hr - PH, ww = hc - PH;
        bool ok = (hh >= 0) && (hh < 32) && (ww >= 0) && (ww < 32);
        size_t off = ok ? ((size_t)(((b << 5) + hh) * 32 + ww) * in_stride + ck * 8) : 0;
        uint32_t sz = ok ? 16u : 0u;
        uint32_t d = (uint32_t)(pos * LDCA + ck * 8) * 2;
        cpa16(sAh + d, inH + off, sz);
        cpa16(sAl + d, inL + off, sz);
    }

    auto issueB = [&](int s, int buf) {
        const int tap = s / NCHK, kc = s - tap * NCHK;
        const char* bu = wp + (size_t)tap * (OC * IC * 4);
#pragma unroll
        for (int i = tid; i < OC * CPRB; i += 256) {
            int rr = i / CPRB, ck = i - rr * CPRB;
            size_t so = (size_t)(rr * IC + kc * CHK + ck * 8) * 2;
            uint32_t d = (uint32_t)(buf * BSZ + rr * LDCB + ck * 8) * 2;
            cpa16(sBh + d, bu + so, 16);
            cpa16(sBl + d, bu + (size_t)OC * IC * 2 + so, 16);
        }
        CP_COMMIT();
    };

    issueB(0, 0);   // commits A + B0 together

    for (int s = 0; s < NSTB; s++) {
        CP_WAIT0();
        __syncthreads();
        if (s + 1 < NSTB) issueB(s + 1, (s + 1) & 1);

        const int tap = s / NCHK, kc = s - tap * NCHK;
        const uint32_t hoffb = (uint32_t)(((tap / KS) * HC + (tap - (tap / KS) * KS)) * LDCAb)
                             + (uint32_t)(kc * CHK) * 2;
        const uint32_t aAh = sAh + hoffb;
        const uint32_t aAl = sAl + hoffb;
        const uint32_t aBh = sBh + (uint32_t)((s & (NBUF - 1)) * BSZ) * 2;
        const uint32_t aBl = sBl + (uint32_t)((s & (NBUF - 1)) * BSZ) * 2;

#pragma unroll
        for (int ks = 0; ks < KSTC; ks++) {
            // ---- load all fragments for this kstep (single-buffered) ----
            uint32_t fah[2][4], fal[2][4];
            uint32_t fbh[NP2 ? NP2 : 1][4], fbl[NP2 ? NP2 : 1][4];
            uint32_t fth[2], ftl[2];
#pragma unroll
            for (int mt = 0; mt < 2; mt++) {
                uint32_t ro = apix[mt] + (uint32_t)ks * 32;
                ldm4(fah[mt], aAh + ro);
                ldm4(fal[mt], aAl + ro);
            }
#pragma unroll
            for (int p = 0; p < NP2; p++) {
                uint32_t ro = (uint32_t)(wn * (OC / 4) + p * 16 + (lane & 15)) * LDCBb
                            + (uint32_t)ks * 32 + ((lane >> 4) * 16);
                ldm4(fbh[p], aBh + ro);
                ldm4(fbl[p], aBl + ro);
            }
            if (TAIL) {
                uint32_t ro = (uint32_t)(wn * (OC / 4) + NP2 * 16 + (lane & 7)) * LDCBb
                            + (uint32_t)ks * 32 + (((lane >> 3) & 1) * 16);
                ldm2(fth, aBh + ro);
                ldm2(ftl, aBl + ro);
            }

            // ---- term-major mma: hh for all tiles, then hl, then lh ----
#pragma unroll
            for (int p = 0; p < NP2; p++)
#pragma unroll
                for (int sub = 0; sub < 2; sub++)
#pragma unroll
                    for (int mt = 0; mt < 2; mt++)
                        mma16816(acc[mt][p * 2 + sub], fah[mt], fbh[p][sub], fbh[p][sub + 2]);
            if (TAIL)
#pragma unroll
                for (int mt = 0; mt < 2; mt++)
                    mma16816(acc[mt][NT - 1], fah[mt], fth[0], fth[1]);

#pragma unroll
            for (int p = 0; p < NP2; p++)
#pragma unroll
                for (int sub = 0; sub < 2; sub++)
#pragma unroll
                    for (int mt = 0; mt < 2; mt++)
                        mma16816(acc[mt][p * 2 + sub], fah[mt], fbl[p][sub], fbl[p][sub + 2]);
            if (TAIL)
#pragma unroll
                for (int mt = 0; mt < 2; mt++)
                    mma16816(acc[mt][NT - 1], fah[mt], ftl[0], ftl[1]);

#pragma unroll
            for (int p = 0; p < NP2; p++)
#pragma unroll
                for (int sub = 0; sub < 2; sub++)
#pragma unroll
                    for (int mt = 0; mt < 2; mt++)
                        mma16816(acc[mt][p * 2 + sub], fal[mt], fbh[p][sub], fbh[p][sub + 2]);
            if (TAIL)
#pragma unroll
                for (int mt = 0; mt < 2; mt++)
                    mma16816(acc[mt][NT - 1], fal[mt], fth[0], fth[1]);
        }
    }

    // ---- epilogue ----
    const int l4 = lane >> 2, l2 = (lane & 3) * 2;
#pragma unroll
    for (int nt = 0; nt < NT; nt++) {
        const int col = wn * (OC / 4) + nt * 8 + l2;
        float b0 = 0.f, b1 = 0.f;
        if (bias) { b0 = bias[col]; b1 = bias[col + 1]; }
#pragma unroll
        for (int mt = 0; mt < 2; mt++) {
            const int pr = p0 + wm * 32 + mt * 16 + l4;
            float* d = acc[mt][nt];
            float v0 = d[0] + b0, v1 = d[1] + b1, v2 = d[2] + b0, v3 = d[3] + b1;
            if (RELU) {
                v0 = fmaxf(v0, 0.f); v1 = fmaxf(v1, 0.f);
                v2 = fmaxf(v2, 0.f); v3 = fmaxf(v3, 0.f);
            }
            if (ADDIN) {
                float2 a0 = *(const float2*)(addp + (size_t)pr * add_stride + col);
                float2 a1 = *(const float2*)(addp + (size_t)(pr + 8) * add_stride + col);
                v0 += a0.x; v1 += a0.y; v2 += a1.x; v3 += a1.y;
            }
            if (out) {
                *(float2*)(out + (size_t)pr * out_stride + col) = make_float2(v0, v1);
                *(float2*)(out + (size_t)(pr + 8) * out_stride + col) = make_float2(v2, v3);
            }
            __nv_bfloat162 h01 = __float22bfloat162_rn(make_float2(v0, v1));
            __nv_bfloat162 h23 = __float22bfloat162_rn(make_float2(v2, v3));
            float2 f01 = __bfloat1622float2(h01);
            float2 f23 = __bfloat1622float2(h23);
            __nv_bfloat162 l01 = __float22bfloat162_rn(make_float2(v0 - f01.x, v1 - f01.y));
            __nv_bfloat162 l23 = __float22bfloat162_rn(make_float2(v2 - f23.x, v3 - f23.y));
            *(__nv_bfloat162*)(outH + (size_t)pr * out_stride + col) = h01;
            *(__nv_bfloat162*)(outH + (size_t)(pr + 8) * out_stride + col) = h23;
            *(__nv_bfloat162*)(outL + (size_t)pr * out_stride + col) = l01;
            *(__nv_bfloat162*)(outL + (size_t)(pr + 8) * out_stride + col) = l23;
        }
    }
}

// ---------------- launch ----------------
extern "C" void kernel_launch(void* const* d_in, const int* in_sizes, int n_in,
                              void* d_out, int out_size) {
    const float* x     = (const float*)d_in[0];
    const float* mu    = (const float*)d_in[1];
    const float* sigma = (const float*)d_in[2];
    const float* wf    = (const float*)d_in[3];
    const float* bfl   = (const float*)d_in[4];
    const float* m     = (const float*)d_in[5];
    const int*   perm  = (const int*)d_in[6];
    float* out = (float*)d_out;

    char *wp, *mp;
    float *Xa, *Xb;
    __nv_bfloat16 *XaH, *XaL, *XbH, *XbL, *T1H, *T1L, *T2H, *T2L;
    cudaGetSymbolAddress((void**)&wp, g_wpc);
    cudaGetSymbolAddress((void**)&mp, g_mpc);
    cudaGetSymbolAddress((void**)&Xa, g_Xa);
    cudaGetSymbolAddress((void**)&Xb, g_Xb);
    cudaGetSymbolAddress((void**)&XaH, g_XaH);
    cudaGetSymbolAddress((void**)&XaL, g_XaL);
    cudaGetSymbolAddress((void**)&XbH, g_XbH);
    cudaGetSymbolAddress((void**)&XbL, g_XbL);
    cudaGetSymbolAddress((void**)&T1H, g_T1H);
    cudaGetSymbolAddress((void**)&T1L, g_T1L);
    cudaGetSymbolAddress((void**)&T2H, g_T2H);
    cudaGetSymbolAddress((void**)&T2L, g_T2L);

    // dynamic smem: 4*NPOS*LDCA + NBUF*4*OC*LDCB
    const int SM_C1 = 4 * (136 * 104) + 2 * 4 * (128 * 104);   // 163,072
    const int SM_C2 = 4 * (136 * 136) + 2 * 4 * (128 * 136);   // 213,248
    const int SM_C3 = 4 * (136 * 136) + 2 * 4 * (96 * 136);    // 178,432
    const int SM_MX = 4 * (64 * 200) + 2 * 4 * (192 * 104);    // 210,944
    static bool attr_done = false;
    if (!attr_done) {
        cudaFuncSetAttribute(k_mma<96, 128, 3, 96, true, false>,   cudaFuncAttributeMaxDynamicSharedMemorySize, SM_C1);
        cudaFuncSetAttribute(k_mma<128, 128, 3, 128, true, false>, cudaFuncAttributeMaxDynamicSharedMemorySize, SM_C2);
        cudaFuncSetAttribute(k_mma<128, 96, 3, 128, false, true>,  cudaFuncAttributeMaxDynamicSharedMemorySize, SM_C3);
        cudaFuncSetAttribute(k_mma<192, 192, 1, 96, false, false>, cudaFuncAttributeMaxDynamicSharedMemorySize, SM_MX);
        attr_done = true;
    }

    k_wp<<<(WTOT + 255) / 256, 256>>>(wf);
    k_mp<<<(32 * 36864 + 255) / 256, 256>>>(m);
    k_pre<<<(NP * 192 + 255) / 256, 256>>>(x, mu, sigma, perm, Xa, XaH, XaL);

    const size_t pre_j[6] = {0, 442368, 1032192, 1474560, 1916928, 2506752};
    const int bstart[6] = {0, 128, 256, 352, 480, 608};

    float* X = Xa;  __nv_bfloat16 *XH = XaH, *XL = XaL;
    float* Y = Xb;  __nv_bfloat16 *YH = XbH, *YL = XbL;
    for (int blk = 0; blk < 32; blk++) {
        const char* wb = wp + (size_t)blk * WP_PER_BLK;
        const float* bb = bfl + blk * 704;
        // round 0: x1 += f0(x2)
        k_mma<96, 128, 3, 96, true, false><<<128, 256, SM_C1>>>(XH + 96, XL + 96, 192, wb + pre_j[0], bb + bstart[0], nullptr, 0, nullptr, T1H, T1L, 128);
        k_mma<128, 128, 3, 128, true, false><<<128, 256, SM_C2>>>(T1H, T1L, 128, wb + pre_j[1], bb + bstart[1], nullptr, 0, nullptr, T2H, T2L, 128);
        k_mma<128, 96, 3, 128, false, true><<<128, 256, SM_C3>>>(T2H, T2L, 128, wb + pre_j[2], bb + bstart[2], X + 0, 192, X + 0, XH + 0, XL + 0, 192);
        // round 1: x2 += f1(x1)
        k_mma<96, 128, 3, 96, true, false><<<128, 256, SM_C1>>>(XH + 0, XL + 0, 192, wb + pre_j[3], bb + bstart[3], nullptr, 0, nullptr, T1H, T1L, 128);
        k_mma<128, 128, 3, 128, true, false><<<128, 256, SM_C2>>>(T1H, T1L, 128, wb + pre_j[4], bb + bstart[4], nullptr, 0, nullptr, T2H, T2L, 128);
        k_mma<128, 96, 3, 128, false, true><<<128, 256, SM_C3>>>(T2H, T2L, 128, wb + pre_j[5], bb + bstart[5], X + 96, 192, X + 96, XH + 96, XL + 96, 192);
        // 1x1 mixing (K chunked 2x96, double-buffered B)
        k_mma<192, 192, 1, 96, false, false><<<128, 256, SM_MX>>>(XH, XL, 192, mp + (size_t)blk * MP_PER_BLK, nullptr, nullptr, 0, Y, YH, YL, 192);
        float* tf = X; X = Y; Y = tf;
        __nv_bfloat16* th = XH; XH = YH; YH = th;
        __nv_bfloat16* tl = XL; XL = YL; YL = tl;
    }

    k_post<<<(NP * 192 + 255) / 256, 256>>>(X, out);
}

// round 13
// speedup vs baseline: 1.2636x; 1.2465x over previous
#include <cuda_runtime.h>
#include <cuda_bf16.h>
#include <cstdint>
#include <cstring>

// ---------------- constants ----------------
constexpr int NP = 8192;
constexpr int WTOT = 23592960;
constexpr int PER_BLK_W = 737280;
constexpr size_t WP_PER_BLK = 2949120;     // 4 bytes per weight (hi+lo bf16)
constexpr size_t MP_PER_BLK = 147456;

// ---------------- device scratch ----------------
__device__ char g_wpc[32 * WP_PER_BLK];
__device__ char g_mpc[32 * MP_PER_BLK];
__device__ float g_Xa[NP * 192], g_Xb[NP * 192];
__device__ __nv_bfloat16 g_XaH[NP * 192], g_XaL[NP * 192];
__device__ __nv_bfloat16 g_XbH[NP * 192], g_XbL[NP * 192];
__device__ __nv_bfloat16 g_T1H[NP * 128], g_T1L[NP * 128];
__device__ __nv_bfloat16 g_T2H[NP * 128], g_T2L[NP * 128];

// ---------------- helpers ----------------
__device__ __forceinline__ uint32_t smem_u32(const void* p) {
    uint32_t a;
    asm("{ .reg .u64 t; cvta.to.shared.u64 t, %1; cvt.u32.u64 %0, t; }" : "=r"(a) : "l"(p));
    return a;
}
__device__ __forceinline__ unsigned short f2bf(float v) {
    __nv_bfloat16 b = __float2bfloat16(v);
    unsigned short u; memcpy(&u, &b, 2);
    return u;
}
__device__ __forceinline__ float bf2f(unsigned short u) {
    __nv_bfloat16 b; memcpy(&b, &u, 2);
    return __bfloat162float(b);
}
__device__ __forceinline__ void ldm4(uint32_t* r, uint32_t addr) {
    asm volatile("ldmatrix.sync.aligned.m8n8.x4.shared.b16 {%0,%1,%2,%3}, [%4];"
        : "=r"(r[0]), "=r"(r[1]), "=r"(r[2]), "=r"(r[3]) : "r"(addr));
}
__device__ __forceinline__ void mma16816(float* d, const uint32_t* a, uint32_t b0, uint32_t b1) {
    asm volatile("mma.sync.aligned.m16n8k16.row.col.f32.bf16.bf16.f32 "
        "{%0,%1,%2,%3},{%4,%5,%6,%7},{%8,%9},{%0,%1,%2,%3};"
        : "+f"(d[0]), "+f"(d[1]), "+f"(d[2]), "+f"(d[3])
        : "r"(a[0]), "r"(a[1]), "r"(a[2]), "r"(a[3]), "r"(b0), "r"(b1));
}
__device__ __forceinline__ void cpa16(uint32_t dst, const void* src, uint32_t srcsz) {
    asm volatile("cp.async.cg.shared.global [%0], [%1], 16, %2;"
        :: "r"(dst), "l"(src), "r"(srcsz) : "memory");
}
#define CP_COMMIT() asm volatile("cp.async.commit_group;" ::: "memory")
#define CP_WAIT0()  asm volatile("cp.async.wait_group 0;" ::: "memory")

// ---------------- weight prepack (convs): mma B-fragment chunks ----------------
// Per conv j: chunks of 512B keyed by ((tap*KST + k16)*(OC/8) + n8tile):
//   [0,256): hi plane, [256,512): lo plane. Within a plane: lane*8 bytes,
//   lane = (o&7)*4 + ((c&7)>>1), byte = ((c>>3)&1)*4 + (c&1)*2.
__global__ void k_wp(const float* __restrict__ wf) {
    int idx = blockIdx.x * 256 + threadIdx.x;
    if (idx >= WTOT) return;
    int blk = idx / PER_BLK_W;
    int r = idx - blk * PER_BLK_W;
    const int starts[6] = {0, 110592, 258048, 368640, 479232, 626688};
    const size_t pre[6] = {0, 442368, 1032192, 1474560, 1916928, 2506752};
    int j = 0;
#pragma unroll
    for (int t = 1; t < 6; t++) if (r >= starts[t]) j = t;
    int off = r - starts[j];
    int oc = ((j % 3) == 2) ? 96 : 128;
    int ic = ((j % 3) == 0) ? 96 : 128;
    int o = off / (ic * 9);
    int rem = off - o * ic * 9;
    int c = rem / 9;
    int tap = rem - c * 9;
    float v = wf[idx];
    unsigned short hb = f2bf(v);
    unsigned short lb = f2bf(v - bf2f(hb));
    int kst = ic >> 4, tiles = oc >> 3;
    int kk = c & 15;
    size_t chunk = (size_t)((tap * kst + (c >> 4)) * tiles + (o >> 3)) * 512;
    size_t e = chunk + (size_t)((o & 7) * 4 + ((kk & 7) >> 1)) * 8
             + ((kk >> 3) & 1) * 4 + (kk & 1) * 2;
    size_t base = (size_t)blk * WP_PER_BLK + pre[j];
    *(unsigned short*)(g_wpc + base + e) = hb;
    *(unsigned short*)(g_wpc + base + 256 + e) = lb;
}

// ---------------- mixing prepack: same fragment-chunk layout ----------------
__global__ void k_mp(const float* __restrict__ m) {
    int idx = blockIdx.x * 256 + threadIdx.x;
    if (idx >= 32 * 36864) return;
    int blk = idx / 36864;
    int r = idx - blk * 36864;
    int o = r / 192, c = r - o * 192;
    float v = m[idx];
    unsigned short hb = f2bf(v);
    unsigned short lb = f2bf(v - bf2f(hb));
    int kk = c & 15;
    size_t chunk = (size_t)((c >> 4) * 24 + (o >> 3)) * 512;
    size_t e = chunk + (size_t)((o & 7) * 4 + ((kk & 7) >> 1)) * 8
             + ((kk >> 3) & 1) * 4 + (kk & 1) * 2;
    size_t base = (size_t)blk * MP_PER_BLK;
    *(unsigned short*)(g_mpc + base + e) = hb;
    *(unsigned short*)(g_mpc + base + 256 + e) = lb;
}

// ---------------- normalize + permute + space_to_depth -> NHWC ----------------
__global__ void k_pre(const float* __restrict__ x, const float* __restrict__ mu,
                      const float* __restrict__ sigma, const int* __restrict__ perm,
                      float* __restrict__ Xo, __nv_bfloat16* __restrict__ XoH,
                      __nv_bfloat16* __restrict__ XoL) {
    int idx = blockIdx.x * 256 + threadIdx.x;
    if (idx >= NP * 192) return;
    int ch = idx % 192;
    int p = idx / 192;
    int w = p & 31, h = (p >> 5) & 31, b = p >> 10;
    int c = ch >> 6, r = ch & 63;
    int bi = r >> 3, bj = r & 7;
    int flat = (h * 8 + bi) * 256 + (w * 8 + bj);
    int src = perm[c * 65536 + flat];
    float v = (x[(b * 3 + c) * 65536 + src] - mu[c]) / sigma[c];
    Xo[idx] = v;
    unsigned short hb = f2bf(v);
    XoH[idx] = *(__nv_bfloat16*)&hb;
    unsigned short lb = f2bf(v - bf2f(hb));
    XoL[idx] = *(__nv_bfloat16*)&lb;
}

// ---------------- final NHWC -> NCHW ----------------
__global__ void k_post(const float* __restrict__ X, float* __restrict__ out) {
    int idx = blockIdx.x * 256 + threadIdx.x;
    if (idx >= NP * 192) return;
    int w = idx & 31;
    int h = (idx >> 5) & 31;
    int ch = (idx >> 10) % 192;
    int b = idx / (192 * 1024);
    out[idx] = X[(((b * 32 + h) * 32 + w) * 192) + ch];
}

// ---------------- warp-mma bf16x3 implicit-GEMM conv ----------------
// CTA = 64 positions x full OC, 8 warps (2M x 4N, warp 32 x OC/4).
// A: halo tile in smem (copied once). B: streamed DIRECTLY from gmem via
// coalesced LDG.64 of prepacked mma-fragment chunks, register-ring buffered
// 2 ksteps ahead. NO barriers / cp.async / smem in the mainloop.
template <int IC, int OC, int KS, bool RELU, bool ADDIN>
__global__ __launch_bounds__(256, 1) void k_mma(
    const __nv_bfloat16* __restrict__ inH, const __nv_bfloat16* __restrict__ inL,
    int in_stride,
    const char* __restrict__ wp,
    const float* __restrict__ bias,
    const float* __restrict__ addp, int add_stride,
    float* __restrict__ out,
    __nv_bfloat16* __restrict__ outH, __nv_bfloat16* __restrict__ outL,
    int out_stride)
{
    constexpr int PH = KS / 2;
    constexpr int HR = 2 + 2 * PH;
    constexpr int HC = 32 + 2 * PH;
    constexpr int NPOS = HR * HC;
    constexpr int NTAP = KS * KS;
    constexpr int KST = IC / 16;          // even for all our shapes
    constexpr int NSTEP = NTAP * KST;
    constexpr int CPRA = IC / 8;
    constexpr int LDCA = IC + 8;
    constexpr int LDCAb = LDCA * 2;
    constexpr int NT = OC / 32;           // n8 tiles per warp
    constexpr int GSTRIDE = (OC / 8) * 512;

    extern __shared__ __align__(16) unsigned short smem[];
    unsigned short* Ah = smem;
    unsigned short* Al = Ah + NPOS * LDCA;

    const int tid = threadIdx.x;
    const int wid = tid >> 5, lane = tid & 31;
    const int wm = wid & 1, wn = wid >> 1;
    const int p0 = blockIdx.x * 64;
    const int b = p0 >> 10;
    const int h0 = (p0 >> 5) & 31;

    float acc[2][NT][4];
#pragma unroll
    for (int i = 0; i < 2; i++)
#pragma unroll
        for (int j = 0; j < NT; j++)
#pragma unroll
            for (int q = 0; q < 4; q++) acc[i][j][q] = 0.f;

    const uint32_t sAh = smem_u32(Ah), sAl = smem_u32(Al);

    uint32_t apix[2];
#pragma unroll
    for (int mt = 0; mt < 2; mt++) {
        int p = wm * 32 + mt * 16 + (lane & 15);
        apix[mt] = (uint32_t)(((p >> 5) * HC + (p & 31)) * LDCAb) + ((lane >> 4) * 16);
    }

    // ---- prologue: A halo copy (once) ----
#pragma unroll 4
    for (int i = tid; i < NPOS * CPRA; i += 256) {
        int pos = i / CPRA, ck = i - pos * CPRA;
        int hr = pos / HC, hc = pos - hr * HC;
        int hh = h0 + hr - PH, ww = hc - PH;
        bool ok = (hh >= 0) && (hh < 32) && (ww >= 0) && (ww < 32);
        size_t off = ok ? ((size_t)(((b << 5) + hh) * 32 + ww) * in_stride + ck * 8) : 0;
        uint32_t sz = ok ? 16u : 0u;
        uint32_t d = (uint32_t)(pos * LDCA + ck * 8) * 2;
        cpa16(sAh + d, inH + off, sz);
        cpa16(sAl + d, inL + off, sz);
    }
    CP_COMMIT();

    // B stream pointers (this warp's chunk row)
    const char* bwarp = wp + (size_t)(wn * NT) * 512 + (size_t)lane * 8;

    uint32_t fah[2][2][4], fal[2][2][4];
    uint2 rbh[2][NT], rbl[2][NT];

    auto ldA = [&](uint32_t aoff, int rb) {
#pragma unroll
        for (int mt = 0; mt < 2; mt++) {
            ldm4(fah[rb][mt], sAh + apix[mt] + aoff);
            ldm4(fal[rb][mt], sAl + apix[mt] + aoff);
        }
    };
    auto ldB = [&](const char* p, uint2* h, uint2* l) {
#pragma unroll
        for (int nt = 0; nt < NT; nt++) {
            h[nt] = *(const uint2*)(p + nt * 512);
            l[nt] = *(const uint2*)(p + nt * 512 + 256);
        }
    };

    // B prefetch (gs 0,1) can start immediately — gmem, no barrier needed
    ldB(bwarp, rbh[0], rbl[0]);
    ldB(bwarp + GSTRIDE, rbh[1], rbl[1]);

    CP_WAIT0();
    __syncthreads();
    ldA(0, 0);   // tap 0 offset = 0, ks 0

    const char* bpre = bwarp + 2 * (size_t)GSTRIDE;
    int gs = 0;

    for (int tap = 0; tap < NTAP; tap++) {
        const uint32_t ac = (uint32_t)(((tap / KS) * HC + (tap - (tap / KS) * KS)) * LDCAb);
        const int tn = (tap + 1 < NTAP) ? tap + 1 : tap;
        const uint32_t an = (uint32_t)(((tn / KS) * HC + (tn - (tn / KS) * KS)) * LDCAb);
#pragma unroll
        for (int ks = 0; ks < KST; ks++) {
            const int pb = ks & 1;           // KST even -> global parity == ks&1
            // prefetch A frags for gs+1
            uint32_t anext = (ks + 1 < KST) ? (ac + (uint32_t)(ks + 1) * 32) : an;
            ldA(anext, pb ^ 1);
            // prefetch B chunks for gs+2 into temps
            uint2 tnh[NT], tnl[NT];
            const char* bp = (gs + 2 < NSTEP) ? bpre : bwarp;
            ldB(bp, tnh, tnl);

            // ---- term-major mma on current frags ----
#pragma unroll
            for (int nt = 0; nt < NT; nt++)
#pragma unroll
                for (int mt = 0; mt < 2; mt++)
                    mma16816(acc[mt][nt], fah[pb][mt], rbh[pb][nt].x, rbh[pb][nt].y);
#pragma unroll
            for (int nt = 0; nt < NT; nt++)
#pragma unroll
                for (int mt = 0; mt < 2; mt++)
                    mma16816(acc[mt][nt], fah[pb][mt], rbl[pb][nt].x, rbl[pb][nt].y);
#pragma unroll
            for (int nt = 0; nt < NT; nt++)
#pragma unroll
                for (int mt = 0; mt < 2; mt++)
                    mma16816(acc[mt][nt], fal[pb][mt], rbh[pb][nt].x, rbh[pb][nt].y);

            // rotate B ring
#pragma unroll
            for (int nt = 0; nt < NT; nt++) { rbh[pb][nt] = tnh[nt]; rbl[pb][nt] = tnl[nt]; }
            bpre += GSTRIDE;
            gs++;
        }
    }

    // ---- epilogue ----
    const int l4 = lane >> 2, l2 = (lane & 3) * 2;
#pragma unroll
    for (int nt = 0; nt < NT; nt++) {
        const int col = wn * (OC / 4) + nt * 8 + l2;
        float b0 = 0.f, b1 = 0.f;
        if (bias) { b0 = bias[col]; b1 = bias[col + 1]; }
#pragma unroll
        for (int mt = 0; mt < 2; mt++) {
            const int pr = p0 + wm * 32 + mt * 16 + l4;
            float* d = acc[mt][nt];
            float v0 = d[0] + b0, v1 = d[1] + b1, v2 = d[2] + b0, v3 = d[3] + b1;
            if (RELU) {
                v0 = fmaxf(v0, 0.f); v1 = fmaxf(v1, 0.f);
                v2 = fmaxf(v2, 0.f); v3 = fmaxf(v3, 0.f);
            }
            if (ADDIN) {
                float2 a0 = *(const float2*)(addp + (size_t)pr * add_stride + col);
                float2 a1 = *(const float2*)(addp + (size_t)(pr + 8) * add_stride + col);
                v0 += a0.x; v1 += a0.y; v2 += a1.x; v3 += a1.y;
            }
            if (out) {
                *(float2*)(out + (size_t)pr * out_stride + col) = make_float2(v0, v1);
                *(float2*)(out + (size_t)(pr + 8) * out_stride + col) = make_float2(v2, v3);
            }
            __nv_bfloat162 h01 = __float22bfloat162_rn(make_float2(v0, v1));
            __nv_bfloat162 h23 = __float22bfloat162_rn(make_float2(v2, v3));
            float2 f01 = __bfloat1622float2(h01);
            float2 f23 = __bfloat1622float2(h23);
            __nv_bfloat162 l01 = __float22bfloat162_rn(make_float2(v0 - f01.x, v1 - f01.y));
            __nv_bfloat162 l23 = __float22bfloat162_rn(make_float2(v2 - f23.x, v3 - f23.y));
            *(__nv_bfloat162*)(outH + (size_t)pr * out_stride + col) = h01;
            *(__nv_bfloat162*)(outH + (size_t)(pr + 8) * out_stride + col) = h23;
            *(__nv_bfloat162*)(outL + (size_t)pr * out_stride + col) = l01;
            *(__nv_bfloat162*)(outL + (size_t)(pr + 8) * out_stride + col) = l23;
        }
    }
}

// ---------------- launch ----------------
extern "C" void kernel_launch(void* const* d_in, const int* in_sizes, int n_in,
                              void* d_out, int out_size) {
    const float* x     = (const float*)d_in[0];
    const float* mu    = (const float*)d_in[1];
    const float* sigma = (const float*)d_in[2];
    const float* wf    = (const float*)d_in[3];
    const float* bfl   = (const float*)d_in[4];
    const float* m     = (const float*)d_in[5];
    const int*   perm  = (const int*)d_in[6];
    float* out = (float*)d_out;

    char *wp, *mp;
    float *Xa, *Xb;
    __nv_bfloat16 *XaH, *XaL, *XbH, *XbL, *T1H, *T1L, *T2H, *T2L;
    cudaGetSymbolAddress((void**)&wp, g_wpc);
    cudaGetSymbolAddress((void**)&mp, g_mpc);
    cudaGetSymbolAddress((void**)&Xa, g_Xa);
    cudaGetSymbolAddress((void**)&Xb, g_Xb);
    cudaGetSymbolAddress((void**)&XaH, g_XaH);
    cudaGetSymbolAddress((void**)&XaL, g_XaL);
    cudaGetSymbolAddress((void**)&XbH, g_XbH);
    cudaGetSymbolAddress((void**)&XbL, g_XbL);
    cudaGetSymbolAddress((void**)&T1H, g_T1H);
    cudaGetSymbolAddress((void**)&T1L, g_T1L);
    cudaGetSymbolAddress((void**)&T2H, g_T2H);
    cudaGetSymbolAddress((void**)&T2L, g_T2L);

    // dynamic smem: A halo only = 4 * NPOS * LDCA bytes
    const int SM_C1 = 4 * (136 * 104);   // 56,576
    const int SM_C2 = 4 * (136 * 136);   // 73,984
    const int SM_C3 = 4 * (136 * 136);   // 73,984
    const int SM_MX = 4 * (64 * 200);    // 51,200
    static bool attr_done = false;
    if (!attr_done) {
        cudaFuncSetAttribute(k_mma<96, 128, 3, true, false>,   cudaFuncAttributeMaxDynamicSharedMemorySize, SM_C1);
        cudaFuncSetAttribute(k_mma<128, 128, 3, true, false>,  cudaFuncAttributeMaxDynamicSharedMemorySize, SM_C2);
        cudaFuncSetAttribute(k_mma<128, 96, 3, false, true>,   cudaFuncAttributeMaxDynamicSharedMemorySize, SM_C3);
        cudaFuncSetAttribute(k_mma<192, 192, 1, false, false>, cudaFuncAttributeMaxDynamicSharedMemorySize, SM_MX);
        attr_done = true;
    }

    k_wp<<<(WTOT + 255) / 256, 256>>>(wf);
    k_mp<<<(32 * 36864 + 255) / 256, 256>>>(m);
    k_pre<<<(NP * 192 + 255) / 256, 256>>>(x, mu, sigma, perm, Xa, XaH, XaL);

    const size_t pre_j[6] = {0, 442368, 1032192, 1474560, 1916928, 2506752};
    const int bstart[6] = {0, 128, 256, 352, 480, 608};

    float* X = Xa;  __nv_bfloat16 *XH = XaH, *XL = XaL;
    float* Y = Xb;  __nv_bfloat16 *YH = XbH, *YL = XbL;
    for (int blk = 0; blk < 32; blk++) {
        const char* wb = wp + (size_t)blk * WP_PER_BLK;
        const float* bb = bfl + blk * 704;
        // round 0: x1 += f0(x2)
        k_mma<96, 128, 3, true, false><<<128, 256, SM_C1>>>(XH + 96, XL + 96, 192, wb + pre_j[0], bb + bstart[0], nullptr, 0, nullptr, T1H, T1L, 128);
        k_mma<128, 128, 3, true, false><<<128, 256, SM_C2>>>(T1H, T1L, 128, wb + pre_j[1], bb + bstart[1], nullptr, 0, nullptr, T2H, T2L, 128);
        k_mma<128, 96, 3, false, true><<<128, 256, SM_C3>>>(T2H, T2L, 128, wb + pre_j[2], bb + bstart[2], X + 0, 192, X + 0, XH + 0, XL + 0, 192);
        // round 1: x2 += f1(x1)
        k_mma<96, 128, 3, true, false><<<128, 256, SM_C1>>>(XH + 0, XL + 0, 192, wb + pre_j[3], bb + bstart[3], nullptr, 0, nullptr, T1H, T1L, 128);
        k_mma<128, 128, 3, true, false><<<128, 256, SM_C2>>>(T1H, T1L, 128, wb + pre_j[4], bb + bstart[4], nullptr, 0, nullptr, T2H, T2L, 128);
        k_mma<128, 96, 3, false, true><<<128, 256, SM_C3>>>(T2H, T2L, 128, wb + pre_j[5], bb + bstart[5], X + 96, 192, X + 96, XH + 96, XL + 96, 192);
        // 1x1 mixing
        k_mma<192, 192, 1, false, false><<<128, 256, SM_MX>>>(XH, XL, 192, mp + (size_t)blk * MP_PER_BLK, nullptr, nullptr, 0, Y, YH, YL, 192);
        float* tf = X; X = Y; Y = tf;
        __nv_bfloat16* th = XH; XH = YH; YH = th;
        __nv_bfloat16* tl = XL; XL = YL; YL = tl;
    }

    k_post<<<(NP * 192 + 255) / 256, 256>>>(X, out);
}

// round 14
// speedup vs baseline: 1.2784x; 1.0117x over previous
#include <cuda_runtime.h>
#include <cuda_bf16.h>
#include <cstdint>
#include <cstring>

// ---------------- constants ----------------
constexpr int NP = 8192;
constexpr int WTOT = 23592960;
constexpr int PER_BLK_W = 737280;
constexpr size_t WP_PER_BLK = 2949120;     // 4 bytes per weight (hi+lo bf16)
constexpr size_t MP_PER_BLK = 147456;

// ---------------- device scratch ----------------
__device__ char g_wpc[32 * WP_PER_BLK];
__device__ char g_mpc[32 * MP_PER_BLK];
__device__ float g_Xa[NP * 192], g_Xb[NP * 192];
__device__ __nv_bfloat16 g_XaH[NP * 192], g_XaL[NP * 192];
__device__ __nv_bfloat16 g_XbH[NP * 192], g_XbL[NP * 192];
__device__ __nv_bfloat16 g_T1H[NP * 128], g_T1L[NP * 128];
__device__ __nv_bfloat16 g_T2H[NP * 128], g_T2L[NP * 128];

// ---------------- helpers ----------------
__device__ __forceinline__ uint32_t smem_u32(const void* p) {
    uint32_t a;
    asm("{ .reg .u64 t; cvta.to.shared.u64 t, %1; cvt.u32.u64 %0, t; }" : "=r"(a) : "l"(p));
    return a;
}
__device__ __forceinline__ unsigned short f2bf(float v) {
    __nv_bfloat16 b = __float2bfloat16(v);
    unsigned short u; memcpy(&u, &b, 2);
    return u;
}
__device__ __forceinline__ float bf2f(unsigned short u) {
    __nv_bfloat16 b; memcpy(&b, &u, 2);
    return __bfloat162float(b);
}
__device__ __forceinline__ void ldm4(uint32_t* r, uint32_t addr) {
    asm volatile("ldmatrix.sync.aligned.m8n8.x4.shared.b16 {%0,%1,%2,%3}, [%4];"
        : "=r"(r[0]), "=r"(r[1]), "=r"(r[2]), "=r"(r[3]) : "r"(addr));
}
__device__ __forceinline__ void mma16816(float* d, const uint32_t* a, uint32_t b0, uint32_t b1) {
    asm volatile("mma.sync.aligned.m16n8k16.row.col.f32.bf16.bf16.f32 "
        "{%0,%1,%2,%3},{%4,%5,%6,%7},{%8,%9},{%0,%1,%2,%3};"
        : "+f"(d[0]), "+f"(d[1]), "+f"(d[2]), "+f"(d[3])
        : "r"(a[0]), "r"(a[1]), "r"(a[2]), "r"(a[3]), "r"(b0), "r"(b1));
}
__device__ __forceinline__ void cpa16(uint32_t dst, const void* src, uint32_t srcsz) {
    asm volatile("cp.async.cg.shared.global [%0], [%1], 16, %2;"
        :: "r"(dst), "l"(src), "r"(srcsz) : "memory");
}
#define CP_COMMIT() asm volatile("cp.async.commit_group;" ::: "memory")
#define CP_WAIT0()  asm volatile("cp.async.wait_group 0;" ::: "memory")

// ---------------- weight prepack (convs): mma B-fragment chunks ----------------
// Per conv j: chunks of 512B keyed by ((tap*KST + k16)*(OC/8) + n8tile):
//   [0,256): hi plane, [256,512): lo plane. Within a plane: lane*8 bytes,
//   lane = (o&7)*4 + ((c&7)>>1), byte = ((c>>3)&1)*4 + (c&1)*2.
__global__ void k_wp(const float* __restrict__ wf) {
    int idx = blockIdx.x * 256 + threadIdx.x;
    if (idx >= WTOT) return;
    int blk = idx / PER_BLK_W;
    int r = idx - blk * PER_BLK_W;
    const int starts[6] = {0, 110592, 258048, 368640, 479232, 626688};
    const size_t pre[6] = {0, 442368, 1032192, 1474560, 1916928, 2506752};
    int j = 0;
#pragma unroll
    for (int t = 1; t < 6; t++) if (r >= starts[t]) j = t;
    int off = r - starts[j];
    int oc = ((j % 3) == 2) ? 96 : 128;
    int ic = ((j % 3) == 0) ? 96 : 128;
    int o = off / (ic * 9);
    int rem = off - o * ic * 9;
    int c = rem / 9;
    int tap = rem - c * 9;
    float v = wf[idx];
    unsigned short hb = f2bf(v);
    unsigned short lb = f2bf(v - bf2f(hb));
    int kst = ic >> 4, tiles = oc >> 3;
    int kk = c & 15;
    size_t chunk = (size_t)((tap * kst + (c >> 4)) * tiles + (o >> 3)) * 512;
    size_t e = chunk + (size_t)((o & 7) * 4 + ((kk & 7) >> 1)) * 8
             + ((kk >> 3) & 1) * 4 + (kk & 1) * 2;
    size_t base = (size_t)blk * WP_PER_BLK + pre[j];
    *(unsigned short*)(g_wpc + base + e) = hb;
    *(unsigned short*)(g_wpc + base + 256 + e) = lb;
}

// ---------------- mixing prepack: same fragment-chunk layout ----------------
__global__ void k_mp(const float* __restrict__ m) {
    int idx = blockIdx.x * 256 + threadIdx.x;
    if (idx >= 32 * 36864) return;
    int blk = idx / 36864;
    int r = idx - blk * 36864;
    int o = r / 192, c = r - o * 192;
    float v = m[idx];
    unsigned short hb = f2bf(v);
    unsigned short lb = f2bf(v - bf2f(hb));
    int kk = c & 15;
    size_t chunk = (size_t)((c >> 4) * 24 + (o >> 3)) * 512;
    size_t e = chunk + (size_t)((o & 7) * 4 + ((kk & 7) >> 1)) * 8
             + ((kk >> 3) & 1) * 4 + (kk & 1) * 2;
    size_t base = (size_t)blk * MP_PER_BLK;
    *(unsigned short*)(g_mpc + base + e) = hb;
    *(unsigned short*)(g_mpc + base + 256 + e) = lb;
}

// ---------------- normalize + permute + space_to_depth -> NHWC ----------------
__global__ void k_pre(const float* __restrict__ x, const float* __restrict__ mu,
                      const float* __restrict__ sigma, const int* __restrict__ perm,
                      float* __restrict__ Xo, __nv_bfloat16* __restrict__ XoH,
                      __nv_bfloat16* __restrict__ XoL) {
    int idx = blockIdx.x * 256 + threadIdx.x;
    if (idx >= NP * 192) return;
    int ch = idx % 192;
    int p = idx / 192;
    int w = p & 31, h = (p >> 5) & 31, b = p >> 10;
    int c = ch >> 6, r = ch & 63;
    int bi = r >> 3, bj = r & 7;
    int flat = (h * 8 + bi) * 256 + (w * 8 + bj);
    int src = perm[c * 65536 + flat];
    float v = (x[(b * 3 + c) * 65536 + src] - mu[c]) / sigma[c];
    Xo[idx] = v;
    unsigned short hb = f2bf(v);
    XoH[idx] = *(__nv_bfloat16*)&hb;
    unsigned short lb = f2bf(v - bf2f(hb));
    XoL[idx] = *(__nv_bfloat16*)&lb;
}

// ---------------- final NHWC -> NCHW ----------------
__global__ void k_post(const float* __restrict__ X, float* __restrict__ out) {
    int idx = blockIdx.x * 256 + threadIdx.x;
    if (idx >= NP * 192) return;
    int w = idx & 31;
    int h = (idx >> 5) & 31;
    int ch = (idx >> 10) % 192;
    int b = idx / (192 * 1024);
    out[idx] = X[(((b * 32 + h) * 32 + w) * 192) + ch];
}

// ---------------- warp-mma bf16x3 implicit-GEMM conv ----------------
// CTA = 64 positions x full OC, 8 warps (2M x 4N, warp 32 x OC/4).
// A: halo tile in smem (copied once). B: streamed DIRECTLY from gmem via
// coalesced LDG.64 into an RD-deep register ring with compile-time slots —
// LDG issued at kstep gs is consumed at kstep gs+RD-1 (no rotation MOVs).
template <int IC, int OC, int KS, bool RELU, bool ADDIN>
__global__ __launch_bounds__(256, 1) void k_mma(
    const __nv_bfloat16* __restrict__ inH, const __nv_bfloat16* __restrict__ inL,
    int in_stride,
    const char* __restrict__ wp,
    const float* __restrict__ bias,
    const float* __restrict__ addp, int add_stride,
    float* __restrict__ out,
    __nv_bfloat16* __restrict__ outH, __nv_bfloat16* __restrict__ outL,
    int out_stride)
{
    constexpr int PH = KS / 2;
    constexpr int HR = 2 + 2 * PH;
    constexpr int HC = 32 + 2 * PH;
    constexpr int NPOS = HR * HC;
    constexpr int NTAP = KS * KS;
    constexpr int KST = IC / 16;
    constexpr int NSTEP = NTAP * KST;
    constexpr int RD = (KST % 3 == 0) ? 3 : 4;   // ring depth; KST % RD == 0
    constexpr int CPRA = IC / 8;
    constexpr int LDCA = IC + 8;
    constexpr int LDCAb = LDCA * 2;
    constexpr int NT = OC / 32;           // n8 tiles per warp
    constexpr int GSTRIDE = (OC / 8) * 512;

    extern __shared__ __align__(16) unsigned short smem[];
    unsigned short* Ah = smem;
    unsigned short* Al = Ah + NPOS * LDCA;

    const int tid = threadIdx.x;
    const int wid = tid >> 5, lane = tid & 31;
    const int wm = wid & 1, wn = wid >> 1;
    const int p0 = blockIdx.x * 64;
    const int b = p0 >> 10;
    const int h0 = (p0 >> 5) & 31;

    float acc[2][NT][4];
#pragma unroll
    for (int i = 0; i < 2; i++)
#pragma unroll
        for (int j = 0; j < NT; j++)
#pragma unroll
            for (int q = 0; q < 4; q++) acc[i][j][q] = 0.f;

    const uint32_t sAh = smem_u32(Ah), sAl = smem_u32(Al);

    uint32_t apix[2];
#pragma unroll
    for (int mt = 0; mt < 2; mt++) {
        int p = wm * 32 + mt * 16 + (lane & 15);
        apix[mt] = (uint32_t)(((p >> 5) * HC + (p & 31)) * LDCAb) + ((lane >> 4) * 16);
    }

    // ---- prologue: A halo copy (once) ----
#pragma unroll 4
    for (int i = tid; i < NPOS * CPRA; i += 256) {
        int pos = i / CPRA, ck = i - pos * CPRA;
        int hr = pos / HC, hc = pos - hr * HC;
        int hh = h0 + hr - PH, ww = hc - PH;
        bool ok = (hh >= 0) && (hh < 32) && (ww >= 0) && (ww < 32);
        size_t off = ok ? ((size_t)(((b << 5) + hh) * 32 + ww) * in_stride + ck * 8) : 0;
        uint32_t sz = ok ? 16u : 0u;
        uint32_t d = (uint32_t)(pos * LDCA + ck * 8) * 2;
        cpa16(sAh + d, inH + off, sz);
        cpa16(sAl + d, inL + off, sz);
    }
    CP_COMMIT();

    // B stream pointers (this warp's chunk row)
    const char* bwarp = wp + (size_t)(wn * NT) * 512 + (size_t)lane * 8;

    uint32_t fah[2][2][4], fal[2][2][4];
    uint2 rbh[RD][NT], rbl[RD][NT];

    auto ldA = [&](uint32_t aoff, int rb) {
#pragma unroll
        for (int mt = 0; mt < 2; mt++) {
            ldm4(fah[rb][mt], sAh + apix[mt] + aoff);
            ldm4(fal[rb][mt], sAl + apix[mt] + aoff);
        }
    };

    // B prologue: steps 0..RD-2 into slots 0..RD-2 (gmem, no barrier needed)
#pragma unroll
    for (int r = 0; r < RD - 1; r++) {
        const char* p = bwarp + (size_t)r * GSTRIDE;
#pragma unroll
        for (int nt = 0; nt < NT; nt++) {
            rbh[r][nt] = *(const uint2*)(p + nt * 512);
            rbl[r][nt] = *(const uint2*)(p + nt * 512 + 256);
        }
    }

    CP_WAIT0();
    __syncthreads();
    ldA(0, 0);   // tap 0, ks 0

    const char* bpre = bwarp + (size_t)(RD - 1) * GSTRIDE;   // next LDG target
    int gs = 0;

    for (int tap = 0; tap < NTAP; tap++) {
        const uint32_t ac = (uint32_t)(((tap / KS) * HC + (tap - (tap / KS) * KS)) * LDCAb);
        const int tn = (tap + 1 < NTAP) ? tap + 1 : tap;
        const uint32_t an = (uint32_t)(((tn / KS) * HC + (tn - (tn / KS) * KS)) * LDCAb);
#pragma unroll
        for (int ks = 0; ks < KST; ks++) {
            const int slot = ks % RD;            // compile-time after unroll
            const int wsl = (ks + RD - 1) % RD;  // slot written this kstep
            const int pb = ks & 1;
            // prefetch A frags for next kstep
            uint32_t anext = (ks + 1 < KST) ? (ac + (uint32_t)(ks + 1) * 32) : an;
            ldA(anext, pb ^ 1);
            // issue LDG for step gs+RD-1 directly into ring slot wsl
            {
                const char* bp = (gs + RD - 1 < NSTEP) ? bpre : bwarp;
#pragma unroll
                for (int nt = 0; nt < NT; nt++) {
                    rbh[wsl][nt] = *(const uint2*)(bp + nt * 512);
                    rbl[wsl][nt] = *(const uint2*)(bp + nt * 512 + 256);
                }
            }

            // ---- term-major mma on slot frags ----
#pragma unroll
            for (int nt = 0; nt < NT; nt++)
#pragma unroll
                for (int mt = 0; mt < 2; mt++)
                    mma16816(acc[mt][nt], fah[pb][mt], rbh[slot][nt].x, rbh[slot][nt].y);
#pragma unroll
            for (int nt = 0; nt < NT; nt++)
#pragma unroll
                for (int mt = 0; mt < 2; mt++)
                    mma16816(acc[mt][nt], fah[pb][mt], rbl[slot][nt].x, rbl[slot][nt].y);
#pragma unroll
            for (int nt = 0; nt < NT; nt++)
#pragma unroll
                for (int mt = 0; mt < 2; mt++)
                    mma16816(acc[mt][nt], fal[pb][mt], rbh[slot][nt].x, rbh[slot][nt].y);

            bpre += GSTRIDE;
            gs++;
        }
    }

    // ---- epilogue ----
    const int l4 = lane >> 2, l2 = (lane & 3) * 2;
#pragma unroll
    for (int nt = 0; nt < NT; nt++) {
        const int col = wn * (OC / 4) + nt * 8 + l2;
        float b0 = 0.f, b1 = 0.f;
        if (bias) { b0 = bias[col]; b1 = bias[col + 1]; }
#pragma unroll
        for (int mt = 0; mt < 2; mt++) {
            const int pr = p0 + wm * 32 + mt * 16 + l4;
            float* d = acc[mt][nt];
            float v0 = d[0] + b0, v1 = d[1] + b1, v2 = d[2] + b0, v3 = d[3] + b1;
            if (RELU) {
                v0 = fmaxf(v0, 0.f); v1 = fmaxf(v1, 0.f);
                v2 = fmaxf(v2, 0.f); v3 = fmaxf(v3, 0.f);
            }
            if (ADDIN) {
                float2 a0 = *(const float2*)(addp + (size_t)pr * add_stride + col);
                float2 a1 = *(const float2*)(addp + (size_t)(pr + 8) * add_stride + col);
                v0 += a0.x; v1 += a0.y; v2 += a1.x; v3 += a1.y;
            }
            if (out) {
                *(float2*)(out + (size_t)pr * out_stride + col) = make_float2(v0, v1);
                *(float2*)(out + (size_t)(pr + 8) * out_stride + col) = make_float2(v2, v3);
            }
            __nv_bfloat162 h01 = __float22bfloat162_rn(make_float2(v0, v1));
            __nv_bfloat162 h23 = __float22bfloat162_rn(make_float2(v2, v3));
            float2 f01 = __bfloat1622float2(h01);
            float2 f23 = __bfloat1622float2(h23);
            __nv_bfloat162 l01 = __float22bfloat162_rn(make_float2(v0 - f01.x, v1 - f01.y));
            __nv_bfloat162 l23 = __float22bfloat162_rn(make_float2(v2 - f23.x, v3 - f23.y));
            *(__nv_bfloat162*)(outH + (size_t)pr * out_stride + col) = h01;
            *(__nv_bfloat162*)(outH + (size_t)(pr + 8) * out_stride + col) = h23;
            *(__nv_bfloat162*)(outL + (size_t)pr * out_stride + col) = l01;
            *(__nv_bfloat162*)(outL + (size_t)(pr + 8) * out_stride + col) = l23;
        }
    }
}

// ---------------- launch ----------------
extern "C" void kernel_launch(void* const* d_in, const int* in_sizes, int n_in,
                              void* d_out, int out_size) {
    const float* x     = (const float*)d_in[0];
    const float* mu    = (const float*)d_in[1];
    const float* sigma = (const float*)d_in[2];
    const float* wf    = (const float*)d_in[3];
    const float* bfl   = (const float*)d_in[4];
    const float* m     = (const float*)d_in[5];
    const int*   perm  = (const int*)d_in[6];
    float* out = (float*)d_out;

    char *wp, *mp;
    float *Xa, *Xb;
    __nv_bfloat16 *XaH, *XaL, *XbH, *XbL, *T1H, *T1L, *T2H, *T2L;
    cudaGetSymbolAddress((void**)&wp, g_wpc);
    cudaGetSymbolAddress((void**)&mp, g_mpc);
    cudaGetSymbolAddress((void**)&Xa, g_Xa);
    cudaGetSymbolAddress((void**)&Xb, g_Xb);
    cudaGetSymbolAddress((void**)&XaH, g_XaH);
    cudaGetSymbolAddress((void**)&XaL, g_XaL);
    cudaGetSymbolAddress((void**)&XbH, g_XbH);
    cudaGetSymbolAddress((void**)&XbL, g_XbL);
    cudaGetSymbolAddress((void**)&T1H, g_T1H);
    cudaGetSymbolAddress((void**)&T1L, g_T1L);
    cudaGetSymbolAddress((void**)&T2H, g_T2H);
    cudaGetSymbolAddress((void**)&T2L, g_T2L);

    // dynamic smem: A halo only = 4 * NPOS * LDCA bytes
    const int SM_C1 = 4 * (136 * 104);   // 56,576
    const int SM_C2 = 4 * (136 * 136);   // 73,984
    const int SM_C3 = 4 * (136 * 136);   // 73,984
    const int SM_MX = 4 * (64 * 200);    // 51,200
    static bool attr_done = false;
    if (!attr_done) {
        cudaFuncSetAttribute(k_mma<96, 128, 3, true, false>,   cudaFuncAttributeMaxDynamicSharedMemorySize, SM_C1);
        cudaFuncSetAttribute(k_mma<128, 128, 3, true, false>,  cudaFuncAttributeMaxDynamicSharedMemorySize, SM_C2);
        cudaFuncSetAttribute(k_mma<128, 96, 3, false, true>,   cudaFuncAttributeMaxDynamicSharedMemorySize, SM_C3);
        cudaFuncSetAttribute(k_mma<192, 192, 1, false, false>, cudaFuncAttributeMaxDynamicSharedMemorySize, SM_MX);
        attr_done = true;
    }

    k_wp<<<(WTOT + 255) / 256, 256>>>(wf);
    k_mp<<<(32 * 36864 + 255) / 256, 256>>>(m);
    k_pre<<<(NP * 192 + 255) / 256, 256>>>(x, mu, sigma, perm, Xa, XaH, XaL);

    const size_t pre_j[6] = {0, 442368, 1032192, 1474560, 1916928, 2506752};
    const int bstart[6] = {0, 128, 256, 352, 480, 608};

    float* X = Xa;  __nv_bfloat16 *XH = XaH, *XL = XaL;
    float* Y = Xb;  __nv_bfloat16 *YH = XbH, *YL = XbL;
    for (int blk = 0; blk < 32; blk++) {
        const char* wb = wp + (size_t)blk * WP_PER_BLK;
        const float* bb = bfl + blk * 704;
        // round 0: x1 += f0(x2)
        k_mma<96, 128, 3, true, false><<<128, 256, SM_C1>>>(XH + 96, XL + 96, 192, wb + pre_j[0], bb + bstart[0], nullptr, 0, nullptr, T1H, T1L, 128);
        k_mma<128, 128, 3, true, false><<<128, 256, SM_C2>>>(T1H, T1L, 128, wb + pre_j[1], bb + bstart[1], nullptr, 0, nullptr, T2H, T2L, 128);
        k_mma<128, 96, 3, false, true><<<128, 256, SM_C3>>>(T2H, T2L, 128, wb + pre_j[2], bb + bstart[2], X + 0, 192, X + 0, XH + 0, XL + 0, 192);
        // round 1: x2 += f1(x1)
        k_mma<96, 128, 3, true, false><<<128, 256, SM_C1>>>(XH + 0, XL + 0, 192, wb + pre_j[3], bb + bstart[3], nullptr, 0, nullptr, T1H, T1L, 128);
        k_mma<128, 128, 3, true, false><<<128, 256, SM_C2>>>(T1H, T1L, 128, wb + pre_j[4], bb + bstart[4], nullptr, 0, nullptr, T2H, T2L, 128);
        k_mma<128, 96, 3, false, true><<<128, 256, SM_C3>>>(T2H, T2L, 128, wb + pre_j[5], bb + bstart[5], X + 96, 192, X + 96, XH + 96, XL + 96, 192);
        // 1x1 mixing
        k_mma<192, 192, 1, false, false><<<128, 256, SM_MX>>>(XH, XL, 192, mp + (size_t)blk * MP_PER_BLK, nullptr, nullptr, 0, Y, YH, YL, 192);
        float* tf = X; X = Y; Y = tf;
        __nv_bfloat16* th = XH; XH = YH; YH = th;
        __nv_bfloat16* tl = XL; XL = YL; YL = tl;
    }

    k_post<<<(NP * 192 + 255) / 256, 256>>>(X, out);
}

// round 15
// speedup vs baseline: 1.2849x; 1.0051x over previous
#include <cuda_runtime.h>
#include <cuda_bf16.h>
#include <cstdint>
#include <cstring>

// ---------------- constants ----------------
constexpr int NP = 8192;
constexpr int WTOT = 23592960;
constexpr int PER_BLK_W = 737280;
constexpr size_t WP_PER_BLK = 2949120;     // 4 bytes per weight (hi+lo bf16)
constexpr size_t MP_PER_BLK = 147456;

// ---------------- device scratch ----------------
__device__ char g_wpc[32 * WP_PER_BLK];
__device__ char g_mpc[32 * MP_PER_BLK];
__device__ float g_Xa[NP * 192], g_Xb[NP * 192];
__device__ __nv_bfloat16 g_XaH[NP * 192], g_XaL[NP * 192];
__device__ __nv_bfloat16 g_XbH[NP * 192], g_XbL[NP * 192];
__device__ __nv_bfloat16 g_T1H[NP * 128], g_T1L[NP * 128];
__device__ __nv_bfloat16 g_T2H[NP * 128], g_T2L[NP * 128];

// ---------------- helpers ----------------
__device__ __forceinline__ uint32_t smem_u32(const void* p) {
    uint32_t a;
    asm("{ .reg .u64 t; cvta.to.shared.u64 t, %1; cvt.u32.u64 %0, t; }" : "=r"(a) : "l"(p));
    return a;
}
__device__ __forceinline__ unsigned short f2bf(float v) {
    __nv_bfloat16 b = __float2bfloat16(v);
    unsigned short u; memcpy(&u, &b, 2);
    return u;
}
__device__ __forceinline__ float bf2f(unsigned short u) {
    __nv_bfloat16 b; memcpy(&b, &u, 2);
    return __bfloat162float(b);
}
__device__ __forceinline__ void ldm4(uint32_t* r, uint32_t addr) {
    asm volatile("ldmatrix.sync.aligned.m8n8.x4.shared.b16 {%0,%1,%2,%3}, [%4];"
        : "=r"(r[0]), "=r"(r[1]), "=r"(r[2]), "=r"(r[3]) : "r"(addr));
}
__device__ __forceinline__ void mma16816(float* d, const uint32_t* a, uint32_t b0, uint32_t b1) {
    asm volatile("mma.sync.aligned.m16n8k16.row.col.f32.bf16.bf16.f32 "
        "{%0,%1,%2,%3},{%4,%5,%6,%7},{%8,%9},{%0,%1,%2,%3};"
        : "+f"(d[0]), "+f"(d[1]), "+f"(d[2]), "+f"(d[3])
        : "r"(a[0]), "r"(a[1]), "r"(a[2]), "r"(a[3]), "r"(b0), "r"(b1));
}
__device__ __forceinline__ void cpa16(uint32_t dst, const void* src, uint32_t srcsz) {
    asm volatile("cp.async.cg.shared.global [%0], [%1], 16, %2;"
        :: "r"(dst), "l"(src), "r"(srcsz) : "memory");
}
#define CP_COMMIT() asm volatile("cp.async.commit_group;" ::: "memory")
#define CP_WAIT0()  asm volatile("cp.async.wait_group 0;" ::: "memory")

// ---------------- weight prepack (convs): mma B-fragment chunks ----------------
// Per conv j: chunks of 512B keyed by ((tap*KST + k16)*(OC/8) + n8tile):
//   [0,256): hi plane, [256,512): lo plane. Within a plane: lane*8 bytes,
//   lane = (o&7)*4 + ((c&7)>>1), byte = ((c>>3)&1)*4 + (c&1)*2.
__global__ void k_wp(const float* __restrict__ wf) {
    int idx = blockIdx.x * 256 + threadIdx.x;
    if (idx >= WTOT) return;
    int blk = idx / PER_BLK_W;
    int r = idx - blk * PER_BLK_W;
    const int starts[6] = {0, 110592, 258048, 368640, 479232, 626688};
    const size_t pre[6] = {0, 442368, 1032192, 1474560, 1916928, 2506752};
    int j = 0;
#pragma unroll
    for (int t = 1; t < 6; t++) if (r >= starts[t]) j = t;
    int off = r - starts[j];
    int oc = ((j % 3) == 2) ? 96 : 128;
    int ic = ((j % 3) == 0) ? 96 : 128;
    int o = off / (ic * 9);
    int rem = off - o * ic * 9;
    int c = rem / 9;
    int tap = rem - c * 9;
    float v = wf[idx];
    unsigned short hb = f2bf(v);
    unsigned short lb = f2bf(v - bf2f(hb));
    int kst = ic >> 4, tiles = oc >> 3;
    int kk = c & 15;
    size_t chunk = (size_t)((tap * kst + (c >> 4)) * tiles + (o >> 3)) * 512;
    size_t e = chunk + (size_t)((o & 7) * 4 + ((kk & 7) >> 1)) * 8
             + ((kk >> 3) & 1) * 4 + (kk & 1) * 2;
    size_t base = (size_t)blk * WP_PER_BLK + pre[j];
    *(unsigned short*)(g_wpc + base + e) = hb;
    *(unsigned short*)(g_wpc + base + 256 + e) = lb;
}

// ---------------- mixing prepack: same fragment-chunk layout ----------------
__global__ void k_mp(const float* __restrict__ m) {
    int idx = blockIdx.x * 256 + threadIdx.x;
    if (idx >= 32 * 36864) return;
    int blk = idx / 36864;
    int r = idx - blk * 36864;
    int o = r / 192, c = r - o * 192;
    float v = m[idx];
    unsigned short hb = f2bf(v);
    unsigned short lb = f2bf(v - bf2f(hb));
    int kk = c & 15;
    size_t chunk = (size_t)((c >> 4) * 24 + (o >> 3)) * 512;
    size_t e = chunk + (size_t)((o & 7) * 4 + ((kk & 7) >> 1)) * 8
             + ((kk >> 3) & 1) * 4 + (kk & 1) * 2;
    size_t base = (size_t)blk * MP_PER_BLK;
    *(unsigned short*)(g_mpc + base + e) = hb;
    *(unsigned short*)(g_mpc + base + 256 + e) = lb;
}

// ---------------- normalize + permute + space_to_depth -> NHWC ----------------
__global__ void k_pre(const float* __restrict__ x, const float* __restrict__ mu,
                      const float* __restrict__ sigma, const int* __restrict__ perm,
                      float* __restrict__ Xo, __nv_bfloat16* __restrict__ XoH,
                      __nv_bfloat16* __restrict__ XoL) {
    int idx = blockIdx.x * 256 + threadIdx.x;
    if (idx >= NP * 192) return;
    int ch = idx % 192;
    int p = idx / 192;
    int w = p & 31, h = (p >> 5) & 31, b = p >> 10;
    int c = ch >> 6, r = ch & 63;
    int bi = r >> 3, bj = r & 7;
    int flat = (h * 8 + bi) * 256 + (w * 8 + bj);
    int src = perm[c * 65536 + flat];
    float v = (x[(b * 3 + c) * 65536 + src] - mu[c]) / sigma[c];
    Xo[idx] = v;
    unsigned short hb = f2bf(v);
    XoH[idx] = *(__nv_bfloat16*)&hb;
    unsigned short lb = f2bf(v - bf2f(hb));
    XoL[idx] = *(__nv_bfloat16*)&lb;
}

// ---------------- final NHWC -> NCHW ----------------
__global__ void k_post(const float* __restrict__ X, float* __restrict__ out) {
    int idx = blockIdx.x * 256 + threadIdx.x;
    if (idx >= NP * 192) return;
    int w = idx & 31;
    int h = (idx >> 5) & 31;
    int ch = (idx >> 10) % 192;
    int b = idx / (192 * 1024);
    out[idx] = X[(((b * 32 + h) * 32 + w) * 192) + ch];
}

// ---------------- warp-mma bf16x3 implicit-GEMM conv, 16 warps ----------------
// CTA = 64 positions x full OC, 512 threads, 16 warps as 4M x 4N:
// warp tile = 16 pos (one m16) x OC/4 cols. A: halo tile in smem (copied
// once). B: streamed from gmem via LDG.64 of prepacked fragment chunks into
// an RD=2 register ring. Barrier-free mainloop; 4 warps/SMSP.
template <int IC, int OC, int KS, bool RELU, bool ADDIN>
__global__ __launch_bounds__(512, 1) void k_mma(
    const __nv_bfloat16* __restrict__ inH, const __nv_bfloat16* __restrict__ inL,
    int in_stride,
    const char* __restrict__ wp,
    const float* __restrict__ bias,
    const float* __restrict__ addp, int add_stride,
    float* __restrict__ out,
    __nv_bfloat16* __restrict__ outH, __nv_bfloat16* __restrict__ outL,
    int out_stride)
{
    constexpr int PH = KS / 2;
    constexpr int HR = 2 + 2 * PH;
    constexpr int HC = 32 + 2 * PH;
    constexpr int NPOS = HR * HC;
    constexpr int NTAP = KS * KS;
    constexpr int KST = IC / 16;          // even for all our shapes
    constexpr int NSTEP = NTAP * KST;
    constexpr int RD = 2;                 // ring depth (KST always even)
    constexpr int CPRA = IC / 8;
    constexpr int LDCA = IC + 8;
    constexpr int LDCAb = LDCA * 2;
    constexpr int NT = OC / 32;           // n8 tiles per warp (warp N = OC/4)
    constexpr int GSTRIDE = (OC / 8) * 512;

    extern __shared__ __align__(16) unsigned short smem[];
    unsigned short* Ah = smem;
    unsigned short* Al = Ah + NPOS * LDCA;

    const int tid = threadIdx.x;
    const int wid = tid >> 5, lane = tid & 31;
    const int wm = wid & 3, wn = wid >> 2;
    const int p0 = blockIdx.x * 64;
    const int b = p0 >> 10;
    const int h0 = (p0 >> 5) & 31;

    float acc[NT][4];
#pragma unroll
    for (int j = 0; j < NT; j++)
#pragma unroll
        for (int q = 0; q < 4; q++) acc[j][q] = 0.f;

    const uint32_t sAh = smem_u32(Ah), sAl = smem_u32(Al);

    // A fragment per-lane halo pixel offset (bytes), single m16 tile
    uint32_t apix;
    {
        int p = wm * 16 + (lane & 15);
        apix = (uint32_t)(((p >> 5) * HC + (p & 31)) * LDCAb) + ((lane >> 4) * 16);
    }

    // ---- prologue: A halo copy (once) ----
#pragma unroll 4
    for (int i = tid; i < NPOS * CPRA; i += 512) {
        int pos = i / CPRA, ck = i - pos * CPRA;
        int hr = pos / HC, hc = pos - hr * HC;
        int hh = h0 + hr - PH, ww = hc - PH;
        bool ok = (hh >= 0) && (hh < 32) && (ww >= 0) && (ww < 32);
        size_t off = ok ? ((size_t)(((b << 5) + hh) * 32 + ww) * in_stride + ck * 8) : 0;
        uint32_t sz = ok ? 16u : 0u;
        uint32_t d = (uint32_t)(pos * LDCA + ck * 8) * 2;
        cpa16(sAh + d, inH + off, sz);
        cpa16(sAl + d, inL + off, sz);
    }
    CP_COMMIT();

    // B stream pointers (this warp's chunk row)
    const char* bwarp = wp + (size_t)(wn * NT) * 512 + (size_t)lane * 8;

    uint32_t fah[2][4], fal[2][4];
    uint2 rbh[RD][NT], rbl[RD][NT];

    auto ldA = [&](uint32_t aoff, int rb) {
        ldm4(fah[rb], sAh + apix + aoff);
        ldm4(fal[rb], sAl + apix + aoff);
    };

    // B prologue: step 0 into slot 0 (gmem, no barrier needed)
#pragma unroll
    for (int nt = 0; nt < NT; nt++) {
        rbh[0][nt] = *(const uint2*)(bwarp + nt * 512);
        rbl[0][nt] = *(const uint2*)(bwarp + nt * 512 + 256);
    }

    CP_WAIT0();
    __syncthreads();
    ldA(0, 0);   // tap 0, ks 0

    const char* bpre = bwarp + (size_t)(RD - 1) * GSTRIDE;   // next LDG target
    int gs = 0;

    for (int tap = 0; tap < NTAP; tap++) {
        const uint32_t ac = (uint32_t)(((tap / KS) * HC + (tap - (tap / KS) * KS)) * LDCAb);
        const int tn = (tap + 1 < NTAP) ? tap + 1 : tap;
        const uint32_t an = (uint32_t)(((tn / KS) * HC + (tn - (tn / KS) * KS)) * LDCAb);
#pragma unroll
        for (int ks = 0; ks < KST; ks++) {
            const int slot = ks % RD;            // compile-time after unroll
            const int wsl = (ks + RD - 1) % RD;  // slot written this kstep
            const int pb = ks & 1;
            // prefetch A frags for next kstep
            uint32_t anext = (ks + 1 < KST) ? (ac + (uint32_t)(ks + 1) * 32) : an;
            ldA(anext, pb ^ 1);
            // issue LDG for step gs+RD-1 directly into ring slot wsl
            {
                const char* bp = (gs + RD - 1 < NSTEP) ? bpre : bwarp;
#pragma unroll
                for (int nt = 0; nt < NT; nt++) {
                    rbh[wsl][nt] = *(const uint2*)(bp + nt * 512);
                    rbl[wsl][nt] = *(const uint2*)(bp + nt * 512 + 256);
                }
            }

            // ---- term-major mma on slot frags ----
#pragma unroll
            for (int nt = 0; nt < NT; nt++)
                mma16816(acc[nt], fah[pb], rbh[slot][nt].x, rbh[slot][nt].y);
#pragma unroll
            for (int nt = 0; nt < NT; nt++)
                mma16816(acc[nt], fah[pb], rbl[slot][nt].x, rbl[slot][nt].y);
#pragma unroll
            for (int nt = 0; nt < NT; nt++)
                mma16816(acc[nt], fal[pb], rbh[slot][nt].x, rbh[slot][nt].y);

            bpre += GSTRIDE;
            gs++;
        }
    }

    // ---- epilogue ----
    const int l4 = lane >> 2, l2 = (lane & 3) * 2;
#pragma unroll
    for (int nt = 0; nt < NT; nt++) {
        const int col = wn * (OC / 4) + nt * 8 + l2;
        float b0 = 0.f, b1 = 0.f;
        if (bias) { b0 = bias[col]; b1 = bias[col + 1]; }
        const int pr = p0 + wm * 16 + l4;
        float* d = acc[nt];
        float v0 = d[0] + b0, v1 = d[1] + b1, v2 = d[2] + b0, v3 = d[3] + b1;
        if (RELU) {
            v0 = fmaxf(v0, 0.f); v1 = fmaxf(v1, 0.f);
            v2 = fmaxf(v2, 0.f); v3 = fmaxf(v3, 0.f);
        }
        if (ADDIN) {
            float2 a0 = *(const float2*)(addp + (size_t)pr * add_stride + col);
            float2 a1 = *(const float2*)(addp + (size_t)(pr + 8) * add_stride + col);
            v0 += a0.x; v1 += a0.y; v2 += a1.x; v3 += a1.y;
        }
        if (out) {
            *(float2*)(out + (size_t)pr * out_stride + col) = make_float2(v0, v1);
            *(float2*)(out + (size_t)(pr + 8) * out_stride + col) = make_float2(v2, v3);
        }
        __nv_bfloat162 h01 = __float22bfloat162_rn(make_float2(v0, v1));
        __nv_bfloat162 h23 = __float22bfloat162_rn(make_float2(v2, v3));
        float2 f01 = __bfloat1622float2(h01);
        float2 f23 = __bfloat1622float2(h23);
        __nv_bfloat162 l01 = __float22bfloat162_rn(make_float2(v0 - f01.x, v1 - f01.y));
        __nv_bfloat162 l23 = __float22bfloat162_rn(make_float2(v2 - f23.x, v3 - f23.y));
        *(__nv_bfloat162*)(outH + (size_t)pr * out_stride + col) = h01;
        *(__nv_bfloat162*)(outH + (size_t)(pr + 8) * out_stride + col) = h23;
        *(__nv_bfloat162*)(outL + (size_t)pr * out_stride + col) = l01;
        *(__nv_bfloat162*)(outL + (size_t)(pr + 8) * out_stride + col) = l23;
    }
}

// ---------------- launch ----------------
extern "C" void kernel_launch(void* const* d_in, const int* in_sizes, int n_in,
                              void* d_out, int out_size) {
    const float* x     = (const float*)d_in[0];
    const float* mu    = (const float*)d_in[1];
    const float* sigma = (const float*)d_in[2];
    const float* wf    = (const float*)d_in[3];
    const float* bfl   = (const float*)d_in[4];
    const float* m     = (const float*)d_in[5];
    const int*   perm  = (const int*)d_in[6];
    float* out = (float*)d_out;

    char *wp, *mp;
    float *Xa, *Xb;
    __nv_bfloat16 *XaH, *XaL, *XbH, *XbL, *T1H, *T1L, *T2H, *T2L;
    cudaGetSymbolAddress((void**)&wp, g_wpc);
    cudaGetSymbolAddress((void**)&mp, g_mpc);
    cudaGetSymbolAddress((void**)&Xa, g_Xa);
    cudaGetSymbolAddress((void**)&Xb, g_Xb);
    cudaGetSymbolAddress((void**)&XaH, g_XaH);
    cudaGetSymbolAddress((void**)&XaL, g_XaL);
    cudaGetSymbolAddress((void**)&XbH, g_XbH);
    cudaGetSymbolAddress((void**)&XbL, g_XbL);
    cudaGetSymbolAddress((void**)&T1H, g_T1H);
    cudaGetSymbolAddress((void**)&T1L, g_T1L);
    cudaGetSymbolAddress((void**)&T2H, g_T2H);
    cudaGetSymbolAddress((void**)&T2L, g_T2L);

    // dynamic smem: A halo only = 4 * NPOS * LDCA bytes
    const int SM_C1 = 4 * (136 * 104);   // 56,576
    const int SM_C2 = 4 * (136 * 136);   // 73,984
    const int SM_C3 = 4 * (136 * 136);   // 73,984
    const int SM_MX = 4 * (64 * 200);    // 51,200
    static bool attr_done = false;
    if (!attr_done) {
        cudaFuncSetAttribute(k_mma<96, 128, 3, true, false>,   cudaFuncAttributeMaxDynamicSharedMemorySize, SM_C1);
        cudaFuncSetAttribute(k_mma<128, 128, 3, true, false>,  cudaFuncAttributeMaxDynamicSharedMemorySize, SM_C2);
        cudaFuncSetAttribute(k_mma<128, 96, 3, false, true>,   cudaFuncAttributeMaxDynamicSharedMemorySize, SM_C3);
        cudaFuncSetAttribute(k_mma<192, 192, 1, false, false>, cudaFuncAttributeMaxDynamicSharedMemorySize, SM_MX);
        attr_done = true;
    }

    k_wp<<<(WTOT + 255) / 256, 256>>>(wf);
    k_mp<<<(32 * 36864 + 255) / 256, 256>>>(m);
    k_pre<<<(NP * 192 + 255) / 256, 256>>>(x, mu, sigma, perm, Xa, XaH, XaL);

    const size_t pre_j[6] = {0, 442368, 1032192, 1474560, 1916928, 2506752};
    const int bstart[6] = {0, 128, 256, 352, 480, 608};

    float* X = Xa;  __nv_bfloat16 *XH = XaH, *XL = XaL;
    float* Y = Xb;  __nv_bfloat16 *YH = XbH, *YL = XbL;
    for (int blk = 0; blk < 32; blk++) {
        const char* wb = wp + (size_t)blk * WP_PER_BLK;
        const float* bb = bfl + blk * 704;
        // round 0: x1 += f0(x2)
        k_mma<96, 128, 3, true, false><<<128, 512, SM_C1>>>(XH + 96, XL + 96, 192, wb + pre_j[0], bb + bstart[0], nullptr, 0, nullptr, T1H, T1L, 128);
        k_mma<128, 128, 3, true, false><<<128, 512, SM_C2>>>(T1H, T1L, 128, wb + pre_j[1], bb + bstart[1], nullptr, 0, nullptr, T2H, T2L, 128);
        k_mma<128, 96, 3, false, true><<<128, 512, SM_C3>>>(T2H, T2L, 128, wb + pre_j[2], bb + bstart[2], X + 0, 192, X + 0, XH + 0, XL + 0, 192);
        // round 1: x2 += f1(x1)
        k_mma<96, 128, 3, true, false><<<128, 512, SM_C1>>>(XH + 0, XL + 0, 192, wb + pre_j[3], bb + bstart[3], nullptr, 0, nullptr, T1H, T1L, 128);
        k_mma<128, 128, 3, true, false><<<128, 512, SM_C2>>>(T1H, T1L, 128, wb + pre_j[4], bb + bstart[4], nullptr, 0, nullptr, T2H, T2L, 128);
        k_mma<128, 96, 3, false, true><<<128, 512, SM_C3>>>(T2H, T2L, 128, wb + pre_j[5], bb + bstart[5], X + 96, 192, X + 96, XH + 96, XL + 96, 192);
        // 1x1 mixing
        k_mma<192, 192, 1, false, false><<<128, 512, SM_MX>>>(XH, XL, 192, mp + (size_t)blk * MP_PER_BLK, nullptr, nullptr, 0, Y, YH, YL, 192);
        float* tf = X; X = Y; Y = tf;
        __nv_bfloat16* th = XH; XH = YH; YH = th;
        __nv_bfloat16* tl = XL; XL = YL; YL = tl;
    }

    k_post<<<(NP * 192 + 255) / 256, 256>>>(X, out);
}